// round 1
// baseline (speedup 1.0000x reference)
#include <cuda_runtime.h>
#include <math.h>

// ---------------- problem constants ----------------
constexpr int NV   = 16384;           // nodes
constexpr int EDG  = 131072;          // edges (without self loops)
constexpr int ETOT = EDG + NV;        // 147456 edges incl self loops
constexpr int HC   = 512;             // HEADS*C
constexpr int CC   = 128;             // C
constexpr int D1   = 513;             // HID+1
constexpr int BB   = 128;             // batch
constexpr int DA   = 2049;            // 4*HID+1

// ---------------- device scratch (static, no runtime alloc) ----------------
__device__ float g_xl[NV * HC];
__device__ float g_xr[NV * HC];
__device__ float g_h2[NV * HC];
__device__ float g_h3[NV * D1];
__device__ float g_e [ETOT * 4];
__device__ int   g_deg[NV];
__device__ int   g_off[NV + 1];
__device__ int   g_cur[NV];
__device__ int   g_srcv[ETOT];
__device__ float g_za[BB * DA];
__device__ float g_z1[BB * DA];
__device__ float g_z2[BB * DA];
__device__ float g_zb[BB * D1];
__device__ float g_z3[BB * D1];
__device__ float g_zf[BB * D1];

// ---------------- CSR build ----------------
__global__ void zero_deg_kernel() {
    int i = blockIdx.x * blockDim.x + threadIdx.x;
    if (i < NV) g_deg[i] = 0;
}

__global__ void hist_kernel(const int* __restrict__ ei) {
    int i = blockIdx.x * blockDim.x + threadIdx.x;
    if (i >= ETOT) return;
    int dst = (i < EDG) ? ei[EDG + i] : (i - EDG);
    atomicAdd(&g_deg[dst], 1);
}

__global__ void scan_kernel() {
    __shared__ int part[1024];
    int t = threadIdx.x;
    int loc[16];
    int s = 0;
#pragma unroll
    for (int i = 0; i < 16; i++) { loc[i] = s; s += g_deg[t * 16 + i]; }
    part[t] = s;
    __syncthreads();
    for (int d = 1; d < 1024; d <<= 1) {
        int v = (t >= d) ? part[t - d] : 0;
        __syncthreads();
        part[t] += v;
        __syncthreads();
    }
    int base = (t > 0) ? part[t - 1] : 0;
#pragma unroll
    for (int i = 0; i < 16; i++) {
        int o = base + loc[i];
        g_off[t * 16 + i] = o;
        g_cur[t * 16 + i] = o;
    }
    if (t == 1023) g_off[NV] = part[1023];
}

__global__ void scatter_kernel(const int* __restrict__ ei) {
    int i = blockIdx.x * blockDim.x + threadIdx.x;
    if (i >= ETOT) return;
    int s, d;
    if (i < EDG) { s = ei[i]; d = ei[EDG + i]; }
    else         { s = d = i - EDG; }
    int p = atomicAdd(&g_cur[d], 1);
    g_srcv[p] = s;
}

// ---------------- big SGEMM: C[M,N] = A[M,K](lda) @ W[K,N] + bias ----------------
__global__ void __launch_bounds__(256) gemm_kernel(
    const float* __restrict__ A, int lda,
    const float* __restrict__ W,
    const float* __restrict__ bias,
    float* __restrict__ C, int M, int Nc, int K)
{
    const int BM = 128, BN = 128, BK = 8;
    __shared__ float As[BK][BM];
    __shared__ float Bs[BK][BN];
    int bm = blockIdx.y * BM;
    int bn = blockIdx.x * BN;
    int tid = threadIdx.x;
    int tx = tid % 16, ty = tid / 16;
    float acc[8][8];
#pragma unroll
    for (int i = 0; i < 8; i++)
#pragma unroll
        for (int j = 0; j < 8; j++) acc[i][j] = 0.f;

    for (int k0 = 0; k0 < K; k0 += BK) {
#pragma unroll
        for (int i = 0; i < 4; i++) {
            int idx = tid + i * 256;
            int kk = idx & 7, mm = idx >> 3;
            int gm_ = bm + mm, gk = k0 + kk;
            As[kk][mm] = (gm_ < M && gk < K) ? A[(size_t)gm_ * lda + gk] : 0.f;
        }
#pragma unroll
        for (int i = 0; i < 4; i++) {
            int idx = tid + i * 256;
            int kk = idx >> 7, nn = idx & 127;
            int gk = k0 + kk, gn = bn + nn;
            Bs[kk][nn] = (gk < K && gn < Nc) ? W[(size_t)gk * Nc + gn] : 0.f;
        }
        __syncthreads();
#pragma unroll
        for (int kk = 0; kk < BK; kk++) {
            float ra[8], rb[8];
#pragma unroll
            for (int i = 0; i < 8; i++) ra[i] = As[kk][ty * 8 + i];
#pragma unroll
            for (int j = 0; j < 8; j++) rb[j] = Bs[kk][tx * 8 + j];
#pragma unroll
            for (int i = 0; i < 8; i++)
#pragma unroll
                for (int j = 0; j < 8; j++) acc[i][j] += ra[i] * rb[j];
        }
        __syncthreads();
    }
#pragma unroll
    for (int i = 0; i < 8; i++) {
        int gm_ = bm + ty * 8 + i;
        if (gm_ >= M) continue;
#pragma unroll
        for (int j = 0; j < 8; j++) {
            int gn = bn + tx * 8 + j;
            if (gn < Nc) C[(size_t)gm_ * Nc + gn] = acc[i][j] + bias[gn];
        }
    }
}

// ---------------- small-M GEMM (MLP tail), 4 rows per thread ----------------
__global__ void gemm_small_kernel(
    const float* __restrict__ A, int lda,
    const float* __restrict__ W,
    const float* __restrict__ bias,
    float* __restrict__ C, int M, int Nc, int K)
{
    int n = blockIdx.x * blockDim.x + threadIdx.x;
    int m0 = blockIdx.y * 4;
    if (n >= Nc || m0 >= M) return;
    const float* a0 = A + (size_t)m0 * lda;
    const float* a1 = a0 + lda;
    const float* a2 = a1 + lda;
    const float* a3 = a2 + lda;
    float s0 = 0.f, s1 = 0.f, s2 = 0.f, s3 = 0.f;
    for (int k = 0; k < K; k++) {
        float w = W[(size_t)k * Nc + n];
        s0 += a0[k] * w; s1 += a1[k] * w; s2 += a2[k] * w; s3 += a3[k] * w;
    }
    float bv = bias[n];
    C[(size_t)(m0 + 0) * Nc + n] = s0 + bv;
    C[(size_t)(m0 + 1) * Nc + n] = s1 + bv;
    C[(size_t)(m0 + 2) * Nc + n] = s2 + bv;
    C[(size_t)(m0 + 3) * Nc + n] = s3 + bv;
}

// ---------------- fused GATv2 layer (per-dst block, warp = head) ----------------
// mode 0: out = gelu(gat + bias)      -> out[NV*512]
// mode 1: out = add_time(gat + bias)  -> out[NV*513]
__global__ void __launch_bounds__(128) gat_kernel(
    const float* __restrict__ xl, const float* __restrict__ xr,
    const float* __restrict__ att, const float* __restrict__ bias,
    float* __restrict__ out, int mode)
{
    int dst = blockIdx.x;
    int w = threadIdx.x >> 5;
    int l = threadIdx.x & 31;
    int start = g_off[dst];
    int end   = g_off[dst + 1];

    float xrr[4], attr[4];
    const float* xrp  = xr  + (size_t)dst * HC + w * CC;
    const float* attp = att + w * CC;
#pragma unroll
    for (int q = 0; q < 4; q++) { xrr[q] = xrp[l + 32 * q]; attr[q] = attp[l + 32 * q]; }

    // pass 1: e per edge + online softmax stats (replicated across lanes)
    float mx = -1e30f, den = 0.f;
    for (int j = start; j < end; j++) {
        int s = g_srcv[j];
        const float* xls = xl + (size_t)s * HC + w * CC;
        float a = 0.f;
#pragma unroll
        for (int q = 0; q < 4; q++) {
            float v = xls[l + 32 * q] + xrr[q];
            v = (v > 0.f) ? v : 0.2f * v;
            a += v * attr[q];
        }
#pragma unroll
        for (int o = 16; o; o >>= 1) a += __shfl_xor_sync(0xffffffffu, a, o);
        if (l == 0) g_e[(size_t)j * 4 + w] = a;
        float nm = fmaxf(mx, a);
        den = den * __expf(mx - nm) + __expf(a - nm);
        mx = nm;
    }
    __syncwarp();

    // pass 2: weighted aggregation of xl[src]
    float acc[4] = {0.f, 0.f, 0.f, 0.f};
    for (int j = start; j < end; j++) {
        int s = g_srcv[j];
        float ex = __expf(g_e[(size_t)j * 4 + w] - mx);
        const float* xls = xl + (size_t)s * HC + w * CC;
#pragma unroll
        for (int q = 0; q < 4; q++) acc[q] += ex * xls[l + 32 * q];
    }
    float inv = 1.0f / (den + 1e-16f);
    float v[4];
    const float* bp = bias + w * CC;
#pragma unroll
    for (int q = 0; q < 4; q++) v[q] = acc[q] * inv + bp[l + 32 * q];

    if (mode == 0) {
        float* op = out + (size_t)dst * HC + w * CC;
#pragma unroll
        for (int q = 0; q < 4; q++) {
            float x = v[q];
            op[l + 32 * q] = 0.5f * x * (1.0f + erff(x * 0.70710678118654752f));
        }
    } else {
        float sq = 0.f;
#pragma unroll
        for (int q = 0; q < 4; q++) sq += v[q] * v[q];
#pragma unroll
        for (int o = 16; o; o >>= 1) sq += __shfl_xor_sync(0xffffffffu, sq, o);
        __shared__ float red[4];
        if (l == 0) red[w] = sq;
        __syncthreads();
        float tot = red[0] + red[1] + red[2] + red[3];
        if (threadIdx.x == 0) out[(size_t)dst * D1] = sqrtf(1.0f + tot);
        float* op = out + (size_t)dst * D1 + 1 + w * CC;
#pragma unroll
        for (int q = 0; q < 4; q++) op[l + 32 * q] = v[q];
    }
}

// ---------------- centroid per batch ----------------
__global__ void __launch_bounds__(256) centroid_kernel(
    const float* __restrict__ h3, float* __restrict__ gm)
{
    int b = blockIdx.x;
    __shared__ float avg[D1];
    const float* basep = h3 + (size_t)b * 128 * D1;
    for (int c = threadIdx.x; c < D1; c += blockDim.x) {
        float s = 0.f;
        for (int r = 0; r < 128; r++) s += basep[(size_t)r * D1 + c];
        avg[c] = s * (1.0f / 128.0f);
    }
    __syncthreads();
    float loc = 0.f;
    for (int c = threadIdx.x; c < D1; c += blockDim.x) {
        float a = avg[c];
        loc += (c == 0) ? -a * a : a * a;
    }
#pragma unroll
    for (int o = 16; o; o >>= 1) loc += __shfl_xor_sync(0xffffffffu, loc, o);
    __shared__ float red[8];
    int w = threadIdx.x >> 5, l = threadIdx.x & 31;
    if (l == 0) red[w] = loc;
    __syncthreads();
    __shared__ float s_invden;
    if (threadIdx.x == 0) {
        float inner = 0.f;
        for (int i = 0; i < 8; i++) inner += red[i];
        s_invden = 1.0f / sqrtf(fmaxf(-inner, 1e-8f));
    }
    __syncthreads();
    float invd = s_invden;
    for (int c = threadIdx.x; c < D1; c += blockDim.x)
        gm[(size_t)b * D1 + c] = avg[c] * invd;
}

// ---------------- llin epilogue (after z@W+b) ----------------
__global__ void __launch_bounds__(256) llin_post_kernel(
    const float* __restrict__ zin, float* __restrict__ zout,
    const float* __restrict__ sptr, int D)
{
    int b = blockIdx.x;
    const float* row = zin + (size_t)b * D;
    float loc = 0.f;
    for (int c = 1 + threadIdx.x; c < D; c += blockDim.x) { float v = row[c]; loc += v * v; }
#pragma unroll
    for (int o = 16; o; o >>= 1) loc += __shfl_xor_sync(0xffffffffu, loc, o);
    __shared__ float red[8];
    int w = threadIdx.x >> 5, l = threadIdx.x & 31;
    if (l == 0) red[w] = loc;
    __syncthreads();
    __shared__ float s_t, s_scale;
    if (threadIdx.x == 0) {
        float sq = 0.f;
        for (int i = 0; i < 8; i++) sq += red[i];
        sq = fmaxf(sq, 1e-8f);
        float z0 = row[0];
        float t = (1.0f / (1.0f + expf(-z0))) * expf(*sptr) + 1.1f;
        s_t = t;
        s_scale = sqrtf((t * t - 1.0f) / sq);
    }
    __syncthreads();
    if (threadIdx.x == 0) zout[(size_t)b * D] = s_t;
    float sc = s_scale;
    for (int c = 1 + threadIdx.x; c < D; c += blockDim.x)
        zout[(size_t)b * D + c] = row[c] * sc;
}

// ---------------- gelu + add_time over z[:,1:] ----------------
__global__ void __launch_bounds__(256) gelu_addtime_kernel(
    const float* __restrict__ zin, float* __restrict__ zout, int D)
{
    int b = blockIdx.x;
    const float* row = zin + (size_t)b * D;
    float* orow = zout + (size_t)b * D;
    float loc = 0.f;
    for (int c = 1 + threadIdx.x; c < D; c += blockDim.x) {
        float x = row[c];
        float g = 0.5f * x * (1.0f + erff(x * 0.70710678118654752f));
        orow[c] = g;
        loc += g * g;
    }
#pragma unroll
    for (int o = 16; o; o >>= 1) loc += __shfl_xor_sync(0xffffffffu, loc, o);
    __shared__ float red[8];
    int w = threadIdx.x >> 5, l = threadIdx.x & 31;
    if (l == 0) red[w] = loc;
    __syncthreads();
    if (threadIdx.x == 0) {
        float tot = 0.f;
        for (int i = 0; i < 8; i++) tot += red[i];
        orow[0] = sqrtf(1.0f + tot);
    }
}

// ---------------- launch ----------------
extern "C" void kernel_launch(void* const* d_in, const int* in_sizes, int n_in,
                              void* d_out, int out_size)
{
    const float* x  = (const float*)d_in[0];
    const int*   ei = (const int*)d_in[1];
    int base = 2;
    if (n_in > 2 && in_sizes[2] == 1) base = 3;   // batch_size scalar present

    const float* Wl1   = (const float*)d_in[base + 0];
    const float* bl1   = (const float*)d_in[base + 1];
    const float* Wr1   = (const float*)d_in[base + 2];
    const float* br1   = (const float*)d_in[base + 3];
    const float* att1  = (const float*)d_in[base + 4];
    const float* bias1 = (const float*)d_in[base + 5];
    const float* Wl2   = (const float*)d_in[base + 6];
    const float* bl2   = (const float*)d_in[base + 7];
    const float* Wr2   = (const float*)d_in[base + 8];
    const float* br2   = (const float*)d_in[base + 9];
    const float* att2  = (const float*)d_in[base + 10];
    const float* bias2 = (const float*)d_in[base + 11];
    const float* Wa    = (const float*)d_in[base + 12];
    const float* ba    = (const float*)d_in[base + 13];
    const float* sa    = (const float*)d_in[base + 14];
    const float* Wb    = (const float*)d_in[base + 15];
    const float* bb    = (const float*)d_in[base + 16];
    const float* sb    = (const float*)d_in[base + 17];
    const float* Wf    = (const float*)d_in[base + 18];
    const float* bf    = (const float*)d_in[base + 19];
    const float* sf    = (const float*)d_in[base + 20];

    float* out = (float*)d_out;

    void* p;
    cudaGetSymbolAddress(&p, g_xl); float* pxl = (float*)p;
    cudaGetSymbolAddress(&p, g_xr); float* pxr = (float*)p;
    cudaGetSymbolAddress(&p, g_h2); float* ph2 = (float*)p;
    cudaGetSymbolAddress(&p, g_h3); float* ph3 = (float*)p;
    cudaGetSymbolAddress(&p, g_za); float* pza = (float*)p;
    cudaGetSymbolAddress(&p, g_z1); float* pz1 = (float*)p;
    cudaGetSymbolAddress(&p, g_z2); float* pz2 = (float*)p;
    cudaGetSymbolAddress(&p, g_zb); float* pzb = (float*)p;
    cudaGetSymbolAddress(&p, g_z3); float* pz3 = (float*)p;
    cudaGetSymbolAddress(&p, g_zf); float* pzf = (float*)p;

    // CSR build
    zero_deg_kernel<<<(NV + 255) / 256, 256>>>();
    hist_kernel<<<(ETOT + 255) / 256, 256>>>(ei);
    scan_kernel<<<1, 1024>>>();
    scatter_kernel<<<(ETOT + 255) / 256, 256>>>(ei);

    dim3 gb((HC + 127) / 128, (NV + 127) / 128);

    // layer 1: A = x[:,1:]  (offset 1, lda 513)
    gemm_kernel<<<gb, 256>>>(x + 1, D1, Wl1, bl1, pxl, NV, HC, 512);
    gemm_kernel<<<gb, 256>>>(x + 1, D1, Wr1, br1, pxr, NV, HC, 512);
    gat_kernel<<<NV, 128>>>(pxl, pxr, att1, bias1, ph2, 0);

    // layer 2
    gemm_kernel<<<gb, 256>>>(ph2, HC, Wl2, bl2, pxl, NV, HC, 512);
    gemm_kernel<<<gb, 256>>>(ph2, HC, Wr2, br2, pxr, NV, HC, 512);
    gat_kernel<<<NV, 128>>>(pxl, pxr, att2, bias2, ph3, 1);

    // centroid -> second half of output
    centroid_kernel<<<BB, 256>>>(ph3, out + (size_t)BB * D1);

    // MLP head on z = hb[:,0,:] = h3 rows with stride 128*513
    gemm_small_kernel<<<dim3((DA + 255) / 256, BB / 4), 256>>>(ph3, 128 * D1, Wa, ba, pza, BB, DA, D1);
    llin_post_kernel<<<BB, 256>>>(pza, pz1, sa, DA);
    gelu_addtime_kernel<<<BB, 256>>>(pz1, pz2, DA);
    gemm_small_kernel<<<dim3((D1 + 255) / 256, BB / 4), 256>>>(pz2, DA, Wb, bb, pzb, BB, D1, DA);
    llin_post_kernel<<<BB, 256>>>(pzb, pz3, sb, D1);
    gemm_small_kernel<<<dim3((D1 + 255) / 256, BB / 4), 256>>>(pz3, D1, Wf, bf, pzf, BB, D1, D1);
    llin_post_kernel<<<BB, 256>>>(pzf, out, sf, D1);

    (void)out_size;
}

// round 4
// speedup vs baseline: 1.4620x; 1.4620x over previous
#include <cuda_runtime.h>
#include <cuda_bf16.h>
#include <stdint.h>
#include <math.h>

// ---------------- problem constants ----------------
constexpr int NV   = 16384;           // nodes
constexpr int EDG  = 131072;          // edges (without self loops)
constexpr int ETOT = EDG + NV;        // 147456 edges incl self loops
constexpr int HC   = 512;             // HEADS*C
constexpr int CC   = 128;             // C
constexpr int D1   = 513;             // HID+1
constexpr int BB   = 128;             // batch
constexpr int DA   = 2049;            // 4*HID+1

// ---------------- device scratch (static, no runtime alloc) ----------------
__device__ float g_xl[NV * HC];
__device__ float g_xr[NV * HC];
__device__ float g_h2[NV * HC];
__device__ float g_h3[NV * D1];
__device__ int   g_deg[NV];
__device__ int   g_off[NV + 1];
__device__ int   g_cur[NV];
__device__ int   g_srcv[ETOT];
__device__ float g_za[BB * DA];
__device__ float g_z1[BB * DA];
__device__ float g_z2[BB * DA];
__device__ float g_zb[BB * D1];
__device__ float g_z3[BB * D1];
__device__ float g_zf[BB * D1];

// ---------------- CSR build ----------------
__global__ void zero_deg_kernel() {
    int i = blockIdx.x * blockDim.x + threadIdx.x;
    if (i < NV) g_deg[i] = 0;
}

__global__ void hist_kernel(const int* __restrict__ ei) {
    int i = blockIdx.x * blockDim.x + threadIdx.x;
    if (i >= ETOT) return;
    int dst = (i < EDG) ? ei[EDG + i] : (i - EDG);
    atomicAdd(&g_deg[dst], 1);
}

__global__ void scan_kernel() {
    __shared__ int part[1024];
    int t = threadIdx.x;
    int loc[16];
    int s = 0;
#pragma unroll
    for (int i = 0; i < 16; i++) { loc[i] = s; s += g_deg[t * 16 + i]; }
    part[t] = s;
    __syncthreads();
    for (int d = 1; d < 1024; d <<= 1) {
        int v = (t >= d) ? part[t - d] : 0;
        __syncthreads();
        part[t] += v;
        __syncthreads();
    }
    int base = (t > 0) ? part[t - 1] : 0;
#pragma unroll
    for (int i = 0; i < 16; i++) {
        int o = base + loc[i];
        g_off[t * 16 + i] = o;
        g_cur[t * 16 + i] = o;
    }
    if (t == 1023) g_off[NV] = part[1023];
}

__global__ void scatter_kernel(const int* __restrict__ ei) {
    int i = blockIdx.x * blockDim.x + threadIdx.x;
    if (i >= ETOT) return;
    int s, d;
    if (i < EDG) { s = ei[i]; d = ei[EDG + i]; }
    else         { s = d = i - EDG; }
    int p = atomicAdd(&g_cur[d], 1);
    g_srcv[p] = s;
}

// ---------------- tensor-core helpers ----------------
__device__ __forceinline__ void ldmat_x4(unsigned (&r)[4], unsigned addr) {
    asm volatile("ldmatrix.sync.aligned.m8n8.x4.shared.b16 {%0,%1,%2,%3}, [%4];"
        : "=r"(r[0]), "=r"(r[1]), "=r"(r[2]), "=r"(r[3]) : "r"(addr));
}
__device__ __forceinline__ void ldmat_x2(unsigned (&r)[2], unsigned addr) {
    asm volatile("ldmatrix.sync.aligned.m8n8.x2.shared.b16 {%0,%1}, [%2];"
        : "=r"(r[0]), "=r"(r[1]) : "r"(addr));
}
__device__ __forceinline__ void mma16816(float (&d)[4], const unsigned (&a)[4], const unsigned (&b)[2]) {
    asm volatile("mma.sync.aligned.m16n8k16.row.col.f32.bf16.bf16.f32 "
        "{%0,%1,%2,%3},{%4,%5,%6,%7},{%8,%9},{%0,%1,%2,%3};"
        : "+f"(d[0]), "+f"(d[1]), "+f"(d[2]), "+f"(d[3])
        : "r"(a[0]), "r"(a[1]), "r"(a[2]), "r"(a[3]), "r"(b[0]), "r"(b[1]));
}

__device__ __forceinline__ unsigned pack_bf2(float a, float b) {
    __nv_bfloat162 h = __floats2bfloat162_rn(a, b);
    return *(unsigned*)&h;
}

__device__ __forceinline__ unsigned smem_u32(const void* p) {
    return (unsigned)__cvta_generic_to_shared(p);
}

// ---------------- big GEMM on tensor cores (bf16 split x3 = ~fp32 accuracy) ----
// C[M,512] = A[M,512](lda) @ W[512,512] + bias;  M = 16384
// CTA tile 128x128, BK=32, 256 threads (8 warps, warp tile 64x32)
constexpr int ASTR = 40;   // bf16 elems per smem row (32 data + 8 pad => 80B rows)

template<bool AL4>
__global__ void __launch_bounds__(256, 2) gemm_tc_kernel(
    const float* __restrict__ A, int lda,
    const float* __restrict__ W,
    const float* __restrict__ bias,
    float* __restrict__ C)
{
    __shared__ __nv_bfloat16 Ah[128 * ASTR];
    __shared__ __nv_bfloat16 Al[128 * ASTR];
    __shared__ __nv_bfloat16 Bh[128 * ASTR];   // stored transposed: [n][k]
    __shared__ __nv_bfloat16 Bl[128 * ASTR];

    const int tid  = threadIdx.x;
    const int lane = tid & 31;
    const int warp = tid >> 5;
    const int wm   = warp >> 2;   // 0..1
    const int wn   = warp & 3;    // 0..3
    const int bm   = blockIdx.y * 128;
    const int bn   = blockIdx.x * 128;
    const int g    = lane >> 2;
    const int t4   = lane & 3;

    float acc[4][4][4];
#pragma unroll
    for (int mt = 0; mt < 4; mt++)
#pragma unroll
        for (int nt = 0; nt < 4; nt++)
#pragma unroll
            for (int q = 0; q < 4; q++) acc[mt][nt][q] = 0.f;

    for (int k0 = 0; k0 < 512; k0 += 32) {
        // ---- load A tile 128x32, split hi/lo ----
#pragma unroll
        for (int i = 0; i < 4; i++) {
            int idx = tid + i * 256;
            int m = idx >> 3, kc = idx & 7;
            const float* ap = A + (size_t)(bm + m) * lda + k0 + kc * 4;
            float v0, v1, v2, v3;
            if (AL4) {
                float4 f = *(const float4*)ap;
                v0 = f.x; v1 = f.y; v2 = f.z; v3 = f.w;
            } else {
                v0 = ap[0]; v1 = ap[1]; v2 = ap[2]; v3 = ap[3];
            }
            __nv_bfloat16 h0 = __float2bfloat16_rn(v0);
            __nv_bfloat16 h1 = __float2bfloat16_rn(v1);
            __nv_bfloat16 h2 = __float2bfloat16_rn(v2);
            __nv_bfloat16 h3 = __float2bfloat16_rn(v3);
            float r0 = v0 - __bfloat162float(h0);
            float r1 = v1 - __bfloat162float(h1);
            float r2 = v2 - __bfloat162float(h2);
            float r3 = v3 - __bfloat162float(h3);
            int sb = m * ASTR + kc * 4;
            *(uint2*)&Ah[sb] = make_uint2(pack_bf2(__bfloat162float(h0), __bfloat162float(h1)),
                                          pack_bf2(__bfloat162float(h2), __bfloat162float(h3)));
            *(uint2*)&Al[sb] = make_uint2(pack_bf2(r0, r1), pack_bf2(r2, r3));
        }
        // ---- load B tile 32x128 -> transpose to [n][k], split hi/lo ----
#pragma unroll
        for (int i = 0; i < 4; i++) {
            int idx = tid + i * 256;
            int kk = idx >> 5, nc = idx & 31;
            const float* wp = W + (size_t)(k0 + kk) * 512 + bn + nc * 4;
            float4 f = *(const float4*)wp;
            float v[4] = {f.x, f.y, f.z, f.w};
#pragma unroll
            for (int j = 0; j < 4; j++) {
                int n = nc * 4 + j;
                __nv_bfloat16 h = __float2bfloat16_rn(v[j]);
                Bh[n * ASTR + kk] = h;
                Bl[n * ASTR + kk] = __float2bfloat16_rn(v[j] - __bfloat162float(h));
            }
        }
        __syncthreads();

        // ---- compute: 2 k-steps of 16 ----
#pragma unroll
        for (int ks = 0; ks < 2; ks++) {
            unsigned bhf[4][2], blf[4][2];
#pragma unroll
            for (int nt = 0; nt < 4; nt++) {
                int n = wn * 32 + nt * 8 + (lane & 7);
                int k = ks * 16 + ((lane >> 3) & 1) * 8;
                ldmat_x2(bhf[nt], smem_u32(&Bh[n * ASTR + k]));
                ldmat_x2(blf[nt], smem_u32(&Bl[n * ASTR + k]));
            }
#pragma unroll
            for (int mt = 0; mt < 4; mt++) {
                int m = wm * 64 + mt * 16 + ((lane >> 3) & 1) * 8 + (lane & 7);
                int k = ks * 16 + ((lane >> 4) & 1) * 8;
                unsigned ahf[4], alf[4];
                ldmat_x4(ahf, smem_u32(&Ah[m * ASTR + k]));
                ldmat_x4(alf, smem_u32(&Al[m * ASTR + k]));
#pragma unroll
                for (int nt = 0; nt < 4; nt++) {
                    mma16816(acc[mt][nt], ahf, bhf[nt]);
                    mma16816(acc[mt][nt], ahf, blf[nt]);
                    mma16816(acc[mt][nt], alf, bhf[nt]);
                }
            }
        }
        __syncthreads();
    }

    // ---- epilogue: + bias, store fp32 ----
#pragma unroll
    for (int mt = 0; mt < 4; mt++) {
#pragma unroll
        for (int nt = 0; nt < 4; nt++) {
            int row = bm + wm * 64 + mt * 16 + g;
            int col = bn + wn * 32 + nt * 8 + 2 * t4;
            float2 bv = *(const float2*)&bias[col];
            float2 o0 = make_float2(acc[mt][nt][0] + bv.x, acc[mt][nt][1] + bv.y);
            float2 o1 = make_float2(acc[mt][nt][2] + bv.x, acc[mt][nt][3] + bv.y);
            *(float2*)&C[(size_t)row * 512 + col] = o0;
            *(float2*)&C[(size_t)(row + 8) * 512 + col] = o1;
        }
    }
}

// ---------------- small-M GEMM (MLP tail), 4 rows per thread ----------------
__global__ void gemm_small_kernel(
    const float* __restrict__ A, int lda,
    const float* __restrict__ W,
    const float* __restrict__ bias,
    float* __restrict__ C, int M, int Nc, int K)
{
    int n = blockIdx.x * blockDim.x + threadIdx.x;
    int m0 = blockIdx.y * 4;
    if (n >= Nc || m0 >= M) return;
    const float* a0 = A + (size_t)m0 * lda;
    const float* a1 = a0 + lda;
    const float* a2 = a1 + lda;
    const float* a3 = a2 + lda;
    float s0 = 0.f, s1 = 0.f, s2 = 0.f, s3 = 0.f;
    for (int k = 0; k < K; k++) {
        float w = W[(size_t)k * Nc + n];
        s0 += a0[k] * w; s1 += a1[k] * w; s2 += a2[k] * w; s3 += a3[k] * w;
    }
    float bv = bias[n];
    C[(size_t)(m0 + 0) * Nc + n] = s0 + bv;
    C[(size_t)(m0 + 1) * Nc + n] = s1 + bv;
    C[(size_t)(m0 + 2) * Nc + n] = s2 + bv;
    C[(size_t)(m0 + 3) * Nc + n] = s3 + bv;
}

// ---------------- fused GATv2 layer, single pass (flash-style) ----------------
// mode 0: out = gelu(gat + bias)      -> out[NV*512]
// mode 1: out = add_time(gat + bias)  -> out[NV*513]
__global__ void __launch_bounds__(128) gat_kernel(
    const float* __restrict__ xl, const float* __restrict__ xr,
    const float* __restrict__ att, const float* __restrict__ bias,
    float* __restrict__ out, int mode)
{
    int dst = blockIdx.x;
    int w = threadIdx.x >> 5;
    int l = threadIdx.x & 31;
    int start = g_off[dst];
    int end   = g_off[dst + 1];

    float xrr[4], attr[4];
    const float* xrp  = xr  + (size_t)dst * HC + w * CC;
    const float* attp = att + w * CC;
#pragma unroll
    for (int q = 0; q < 4; q++) { xrr[q] = xrp[l + 32 * q]; attr[q] = attp[l + 32 * q]; }

    float mx = -1e30f, den = 0.f;
    float acc[4] = {0.f, 0.f, 0.f, 0.f};

    for (int j = start; j < end; j++) {
        int s = g_srcv[j];
        const float* xls = xl + (size_t)s * HC + w * CC;
        float xv[4];
        float a = 0.f;
#pragma unroll
        for (int q = 0; q < 4; q++) {
            float x = xls[l + 32 * q];
            xv[q] = x;
            float v = x + xrr[q];
            v = (v > 0.f) ? v : 0.2f * v;
            a += v * attr[q];
        }
#pragma unroll
        for (int o = 16; o; o >>= 1) a += __shfl_xor_sync(0xffffffffu, a, o);
        float nm = fmaxf(mx, a);
        float sc = __expf(mx - nm);   // 0 on first edge (mx = -1e30)
        float ew = __expf(a - nm);
        den = den * sc + ew;
#pragma unroll
        for (int q = 0; q < 4; q++) acc[q] = acc[q] * sc + ew * xv[q];
        mx = nm;
    }

    float inv = 1.0f / (den + 1e-16f);
    float v[4];
    const float* bp = bias + w * CC;
#pragma unroll
    for (int q = 0; q < 4; q++) v[q] = acc[q] * inv + bp[l + 32 * q];

    if (mode == 0) {
        float* op = out + (size_t)dst * HC + w * CC;
#pragma unroll
        for (int q = 0; q < 4; q++) {
            float x = v[q];
            op[l + 32 * q] = 0.5f * x * (1.0f + erff(x * 0.70710678118654752f));
        }
    } else {
        float sq = 0.f;
#pragma unroll
        for (int q = 0; q < 4; q++) sq += v[q] * v[q];
#pragma unroll
        for (int o = 16; o; o >>= 1) sq += __shfl_xor_sync(0xffffffffu, sq, o);
        __shared__ float red[4];
        if (l == 0) red[w] = sq;
        __syncthreads();
        float tot = red[0] + red[1] + red[2] + red[3];
        if (threadIdx.x == 0) out[(size_t)dst * D1] = sqrtf(1.0f + tot);
        float* op = out + (size_t)dst * D1 + 1 + w * CC;
#pragma unroll
        for (int q = 0; q < 4; q++) op[l + 32 * q] = v[q];
    }
}

// ---------------- centroid per batch ----------------
__global__ void __launch_bounds__(256) centroid_kernel(
    const float* __restrict__ h3, float* __restrict__ gm)
{
    int b = blockIdx.x;
    __shared__ float avg[D1];
    const float* basep = h3 + (size_t)b * 128 * D1;
    for (int c = threadIdx.x; c < D1; c += blockDim.x) {
        float s = 0.f;
        for (int r = 0; r < 128; r++) s += basep[(size_t)r * D1 + c];
        avg[c] = s * (1.0f / 128.0f);
    }
    __syncthreads();
    float loc = 0.f;
    for (int c = threadIdx.x; c < D1; c += blockDim.x) {
        float a = avg[c];
        loc += (c == 0) ? -a * a : a * a;
    }
#pragma unroll
    for (int o = 16; o; o >>= 1) loc += __shfl_xor_sync(0xffffffffu, loc, o);
    __shared__ float red[8];
    int w = threadIdx.x >> 5, l = threadIdx.x & 31;
    if (l == 0) red[w] = loc;
    __syncthreads();
    __shared__ float s_invden;
    if (threadIdx.x == 0) {
        float inner = 0.f;
        for (int i = 0; i < 8; i++) inner += red[i];
        s_invden = 1.0f / sqrtf(fmaxf(-inner, 1e-8f));
    }
    __syncthreads();
    float invd = s_invden;
    for (int c = threadIdx.x; c < D1; c += blockDim.x)
        gm[(size_t)b * D1 + c] = avg[c] * invd;
}

// ---------------- llin epilogue (after z@W+b) ----------------
__global__ void __launch_bounds__(256) llin_post_kernel(
    const float* __restrict__ zin, float* __restrict__ zout,
    const float* __restrict__ sptr, int D)
{
    int b = blockIdx.x;
    const float* row = zin + (size_t)b * D;
    float loc = 0.f;
    for (int c = 1 + threadIdx.x; c < D; c += blockDim.x) { float v = row[c]; loc += v * v; }
#pragma unroll
    for (int o = 16; o; o >>= 1) loc += __shfl_xor_sync(0xffffffffu, loc, o);
    __shared__ float red[8];
    int w = threadIdx.x >> 5, l = threadIdx.x & 31;
    if (l == 0) red[w] = loc;
    __syncthreads();
    __shared__ float s_t, s_scale;
    if (threadIdx.x == 0) {
        float sq = 0.f;
        for (int i = 0; i < 8; i++) sq += red[i];
        sq = fmaxf(sq, 1e-8f);
        float z0 = row[0];
        float t = (1.0f / (1.0f + expf(-z0))) * expf(*sptr) + 1.1f;
        s_t = t;
        s_scale = sqrtf((t * t - 1.0f) / sq);
    }
    __syncthreads();
    if (threadIdx.x == 0) zout[(size_t)b * D] = s_t;
    float sc = s_scale;
    for (int c = 1 + threadIdx.x; c < D; c += blockDim.x)
        zout[(size_t)b * D + c] = row[c] * sc;
}

// ---------------- gelu + add_time over z[:,1:] ----------------
__global__ void __launch_bounds__(256) gelu_addtime_kernel(
    const float* __restrict__ zin, float* __restrict__ zout, int D)
{
    int b = blockIdx.x;
    const float* row = zin + (size_t)b * D;
    float* orow = zout + (size_t)b * D;
    float loc = 0.f;
    for (int c = 1 + threadIdx.x; c < D; c += blockDim.x) {
        float x = row[c];
        float g = 0.5f * x * (1.0f + erff(x * 0.70710678118654752f));
        orow[c] = g;
        loc += g * g;
    }
#pragma unroll
    for (int o = 16; o; o >>= 1) loc += __shfl_xor_sync(0xffffffffu, loc, o);
    __shared__ float red[8];
    int w = threadIdx.x >> 5, l = threadIdx.x & 31;
    if (l == 0) red[w] = loc;
    __syncthreads();
    if (threadIdx.x == 0) {
        float tot = 0.f;
        for (int i = 0; i < 8; i++) tot += red[i];
        orow[0] = sqrtf(1.0f + tot);
    }
}

// ---------------- launch ----------------
extern "C" void kernel_launch(void* const* d_in, const int* in_sizes, int n_in,
                              void* d_out, int out_size)
{
    const float* x  = (const float*)d_in[0];
    const int*   ei = (const int*)d_in[1];
    int base = 2;
    if (n_in > 2 && in_sizes[2] == 1) base = 3;   // batch_size scalar present

    const float* Wl1   = (const float*)d_in[base + 0];
    const float* bl1   = (const float*)d_in[base + 1];
    const float* Wr1   = (const float*)d_in[base + 2];
    const float* br1   = (const float*)d_in[base + 3];
    const float* att1  = (const float*)d_in[base + 4];
    const float* bias1 = (const float*)d_in[base + 5];
    const float* Wl2   = (const float*)d_in[base + 6];
    const float* bl2   = (const float*)d_in[base + 7];
    const float* Wr2   = (const float*)d_in[base + 8];
    const float* br2   = (const float*)d_in[base + 9];
    const float* att2  = (const float*)d_in[base + 10];
    const float* bias2 = (const float*)d_in[base + 11];
    const float* Wa    = (const float*)d_in[base + 12];
    const float* ba    = (const float*)d_in[base + 13];
    const float* sa    = (const float*)d_in[base + 14];
    const float* Wb    = (const float*)d_in[base + 15];
    const float* bb    = (const float*)d_in[base + 16];
    const float* sb    = (const float*)d_in[base + 17];
    const float* Wf    = (const float*)d_in[base + 18];
    const float* bf    = (const float*)d_in[base + 19];
    const float* sf    = (const float*)d_in[base + 20];

    float* out = (float*)d_out;

    void* p;
    cudaGetSymbolAddress(&p, g_xl); float* pxl = (float*)p;
    cudaGetSymbolAddress(&p, g_xr); float* pxr = (float*)p;
    cudaGetSymbolAddress(&p, g_h2); float* ph2 = (float*)p;
    cudaGetSymbolAddress(&p, g_h3); float* ph3 = (float*)p;
    cudaGetSymbolAddress(&p, g_za); float* pza = (float*)p;
    cudaGetSymbolAddress(&p, g_z1); float* pz1 = (float*)p;
    cudaGetSymbolAddress(&p, g_z2); float* pz2 = (float*)p;
    cudaGetSymbolAddress(&p, g_zb); float* pzb = (float*)p;
    cudaGetSymbolAddress(&p, g_z3); float* pz3 = (float*)p;
    cudaGetSymbolAddress(&p, g_zf); float* pzf = (float*)p;

    // CSR build
    zero_deg_kernel<<<(NV + 255) / 256, 256>>>();
    hist_kernel<<<(ETOT + 255) / 256, 256>>>(ei);
    scan_kernel<<<1, 1024>>>();
    scatter_kernel<<<(ETOT + 255) / 256, 256>>>(ei);

    dim3 gb(4, 128);   // N/128 x M/128

    // layer 1: A = x[:,1:]  (offset 1, lda 513 -> unaligned, scalar loads)
    gemm_tc_kernel<false><<<gb, 256>>>(x + 1, D1, Wl1, bl1, pxl);
    gemm_tc_kernel<false><<<gb, 256>>>(x + 1, D1, Wr1, br1, pxr);
    gat_kernel<<<NV, 128>>>(pxl, pxr, att1, bias1, ph2, 0);

    // layer 2 (lda 512 aligned -> float4 loads)
    gemm_tc_kernel<true><<<gb, 256>>>(ph2, HC, Wl2, bl2, pxl);
    gemm_tc_kernel<true><<<gb, 256>>>(ph2, HC, Wr2, br2, pxr);
    gat_kernel<<<NV, 128>>>(pxl, pxr, att2, bias2, ph3, 1);

    // centroid -> second half of output
    centroid_kernel<<<BB, 256>>>(ph3, out + (size_t)BB * D1);

    // MLP head on z = hb[:,0,:] = h3 rows with stride 128*513
    gemm_small_kernel<<<dim3((DA + 255) / 256, BB / 4), 256>>>(ph3, 128 * D1, Wa, ba, pza, BB, DA, D1);
    llin_post_kernel<<<BB, 256>>>(pza, pz1, sa, DA);
    gelu_addtime_kernel<<<BB, 256>>>(pz1, pz2, DA);
    gemm_small_kernel<<<dim3((D1 + 255) / 256, BB / 4), 256>>>(pz2, DA, Wb, bb, pzb, BB, D1, DA);
    llin_post_kernel<<<BB, 256>>>(pzb, pz3, sb, D1);
    gemm_small_kernel<<<dim3((D1 + 255) / 256, BB / 4), 256>>>(pz3, D1, Wf, bf, pzf, BB, D1, D1);
    llin_post_kernel<<<BB, 256>>>(pzf, out, sf, D1);

    (void)out_size;
}

// round 5
// speedup vs baseline: 1.9935x; 1.3636x over previous
#include <cuda_runtime.h>
#include <cuda_bf16.h>
#include <stdint.h>
#include <math.h>

// ---------------- problem constants ----------------
constexpr int NV   = 16384;           // nodes
constexpr int EDG  = 131072;          // edges (without self loops)
constexpr int ETOT = EDG + NV;        // 147456 edges incl self loops
constexpr int HC   = 512;             // HEADS*C
constexpr int CC   = 128;             // C
constexpr int D1   = 513;             // HID+1
constexpr int BB   = 128;             // batch
constexpr int DA   = 2049;            // 4*HID+1

// ---------------- device scratch (static, no runtime alloc) ----------------
__device__ float g_xl[NV * HC];
__device__ float g_xr[NV * HC];
__device__ float g_h2[NV * HC];
__device__ float g_h3[NV * D1];
__device__ int   g_deg[NV];
__device__ int   g_off[NV + 1];
__device__ int   g_cur[NV];
__device__ int   g_srcv[ETOT];
__device__ float g_za[BB * DA];
__device__ float g_z1[BB * DA];
__device__ float g_z2[BB * DA];
__device__ float g_zb[BB * D1];
__device__ float g_z3[BB * D1];
__device__ float g_zf[BB * D1];
// pre-split bf16 operands
__device__ __nv_bfloat16 g_Ah[NV * HC];
__device__ __nv_bfloat16 g_Al[NV * HC];
__device__ __nv_bfloat16 g_Wth[HC * HC];   // W^T hi  [n][k]
__device__ __nv_bfloat16 g_Wtl[HC * HC];   // W^T lo  [n][k]

// ---------------- CSR build ----------------
__global__ void zero_deg_kernel() {
    int i = blockIdx.x * blockDim.x + threadIdx.x;
    if (i < NV) g_deg[i] = 0;
}

__global__ void hist_kernel(const int* __restrict__ ei) {
    int i = blockIdx.x * blockDim.x + threadIdx.x;
    if (i >= ETOT) return;
    int dst = (i < EDG) ? ei[EDG + i] : (i - EDG);
    atomicAdd(&g_deg[dst], 1);
}

__global__ void scan_kernel() {
    __shared__ int part[1024];
    int t = threadIdx.x;
    int loc[16];
    int s = 0;
#pragma unroll
    for (int i = 0; i < 16; i++) { loc[i] = s; s += g_deg[t * 16 + i]; }
    part[t] = s;
    __syncthreads();
    for (int d = 1; d < 1024; d <<= 1) {
        int v = (t >= d) ? part[t - d] : 0;
        __syncthreads();
        part[t] += v;
        __syncthreads();
    }
    int base = (t > 0) ? part[t - 1] : 0;
#pragma unroll
    for (int i = 0; i < 16; i++) {
        int o = base + loc[i];
        g_off[t * 16 + i] = o;
        g_cur[t * 16 + i] = o;
    }
    if (t == 1023) g_off[NV] = part[1023];
}

__global__ void scatter_kernel(const int* __restrict__ ei) {
    int i = blockIdx.x * blockDim.x + threadIdx.x;
    if (i >= ETOT) return;
    int s, d;
    if (i < EDG) { s = ei[i]; d = ei[EDG + i]; }
    else         { s = d = i - EDG; }
    int p = atomicAdd(&g_cur[d], 1);
    g_srcv[p] = s;
}

// ---------------- helpers ----------------
__device__ __forceinline__ void ldmat_x4(unsigned (&r)[4], unsigned addr) {
    asm volatile("ldmatrix.sync.aligned.m8n8.x4.shared.b16 {%0,%1,%2,%3}, [%4];"
        : "=r"(r[0]), "=r"(r[1]), "=r"(r[2]), "=r"(r[3]) : "r"(addr));
}
__device__ __forceinline__ void ldmat_x2(unsigned (&r)[2], unsigned addr) {
    asm volatile("ldmatrix.sync.aligned.m8n8.x2.shared.b16 {%0,%1}, [%2];"
        : "=r"(r[0]), "=r"(r[1]) : "r"(addr));
}
__device__ __forceinline__ void mma16816(float (&d)[4], const unsigned (&a)[4], const unsigned (&b)[2]) {
    asm volatile("mma.sync.aligned.m16n8k16.row.col.f32.bf16.bf16.f32 "
        "{%0,%1,%2,%3},{%4,%5,%6,%7},{%8,%9},{%0,%1,%2,%3};"
        : "+f"(d[0]), "+f"(d[1]), "+f"(d[2]), "+f"(d[3])
        : "r"(a[0]), "r"(a[1]), "r"(a[2]), "r"(a[3]), "r"(b[0]), "r"(b[1]));
}
__device__ __forceinline__ unsigned smem_u32(const void* p) {
    return (unsigned)__cvta_generic_to_shared(p);
}
__device__ __forceinline__ void cp16(unsigned saddr, const void* g) {
    asm volatile("cp.async.cg.shared.global [%0], [%1], 16;" :: "r"(saddr), "l"(g));
}

// ---------------- pre-split kernels ----------------
// A[M,512] fp32 (lda) -> dense bf16 hi/lo [M*512]
__global__ void splitA_kernel(const float* __restrict__ A, int lda,
                              __nv_bfloat16* __restrict__ Ah, __nv_bfloat16* __restrict__ Al) {
    int i = blockIdx.x * blockDim.x + threadIdx.x;     // NV*128 workers, 4 elems each
    if (i >= NV * 128) return;
    int row = i >> 7, c4 = (i & 127) * 4;
    const float* ap = A + (size_t)row * lda + c4;
    float v0 = ap[0], v1 = ap[1], v2 = ap[2], v3 = ap[3];
    __nv_bfloat16 h0 = __float2bfloat16_rn(v0), h1 = __float2bfloat16_rn(v1);
    __nv_bfloat16 h2 = __float2bfloat16_rn(v2), h3 = __float2bfloat16_rn(v3);
    __nv_bfloat162 H0 = {h0, h1}, H1 = {h2, h3};
    __nv_bfloat162 L0 = {__float2bfloat16_rn(v0 - __bfloat162float(h0)),
                         __float2bfloat16_rn(v1 - __bfloat162float(h1))};
    __nv_bfloat162 L1 = {__float2bfloat16_rn(v2 - __bfloat162float(h2)),
                         __float2bfloat16_rn(v3 - __bfloat162float(h3))};
    size_t o = (size_t)row * 512 + c4;
    *(uint2*)&Ah[o] = make_uint2(*(unsigned*)&H0, *(unsigned*)&H1);
    *(uint2*)&Al[o] = make_uint2(*(unsigned*)&L0, *(unsigned*)&L1);
}

// W[512,512] (k-major) -> W^T bf16 hi/lo [n][k]
__global__ void splitWT_kernel(const float* __restrict__ W,
                               __nv_bfloat16* __restrict__ Th, __nv_bfloat16* __restrict__ Tl) {
    __shared__ float t[32][33];
    int bn = blockIdx.x * 32, bk = blockIdx.y * 32;
    int tx = threadIdx.x, ty = threadIdx.y;            // (32, 8)
#pragma unroll
    for (int i = 0; i < 4; i++) {
        int k = bk + ty + i * 8;
        t[ty + i * 8][tx] = W[(size_t)k * 512 + bn + tx];
    }
    __syncthreads();
#pragma unroll
    for (int i = 0; i < 4; i++) {
        int n = bn + ty + i * 8;
        float v = t[tx][ty + i * 8];
        __nv_bfloat16 h = __float2bfloat16_rn(v);
        Th[(size_t)n * 512 + bk + tx] = h;
        Tl[(size_t)n * 512 + bk + tx] = __float2bfloat16_rn(v - __bfloat162float(h));
    }
}

// ---------------- big GEMM: pure cp.async + ldmatrix + mma, double buffered ----
// C[16384,512] = A @ W + bias with bf16 split-x3 ( ~fp32 accuracy )
constexpr int ASTR = 40;                 // bf16 per smem row (32 data + 8 pad)
constexpr int TILE_E = 128 * ASTR;       // 5120 elems = 10240 B per array
constexpr int GEMM_SMEM = 2 * 4 * TILE_E * 2;   // 81920 B

__global__ void __launch_bounds__(256, 2) gemm_bf16x3_kernel(
    const __nv_bfloat16* __restrict__ Ah, const __nv_bfloat16* __restrict__ Al,
    const __nv_bfloat16* __restrict__ Bh, const __nv_bfloat16* __restrict__ Bl,
    const float* __restrict__ bias, float* __restrict__ C)
{
    extern __shared__ __nv_bfloat16 smem[];
    const int tid  = threadIdx.x;
    const int lane = tid & 31;
    const int warp = tid >> 5;
    const int wm   = warp >> 2;   // 0..1
    const int wn   = warp & 3;    // 0..3
    const int bm   = blockIdx.y * 128;
    const int bn   = blockIdx.x * 128;

    const __nv_bfloat16* gsrc[4] = { Ah + (size_t)bm * 512, Al + (size_t)bm * 512,
                                     Bh + (size_t)bn * 512, Bl + (size_t)bn * 512 };

    float acc[4][4][4];
#pragma unroll
    for (int mt = 0; mt < 4; mt++)
#pragma unroll
        for (int nt = 0; nt < 4; nt++)
#pragma unroll
            for (int q = 0; q < 4; q++) acc[mt][nt][q] = 0.f;

    // per tile: each thread loads 2 16B-chunks per array (512 chunks / 256 thr)
    const int chunk0 = tid * 2;
    const int row0 = chunk0 >> 2, cc0 = (chunk0 & 3) * 8;
    const int row1 = (chunk0 + 1) >> 2, cc1 = ((chunk0 + 1) & 3) * 8;

    auto load_tile = [&](int buf, int k0) {
#pragma unroll
        for (int arr = 0; arr < 4; arr++) {
            __nv_bfloat16* s = smem + (buf * 4 + arr) * TILE_E;
            cp16(smem_u32(s + row0 * ASTR + cc0), gsrc[arr] + (size_t)row0 * 512 + k0 + cc0);
            cp16(smem_u32(s + row1 * ASTR + cc1), gsrc[arr] + (size_t)row1 * 512 + k0 + cc1);
        }
        asm volatile("cp.async.commit_group;");
    };

    load_tile(0, 0);

    for (int t = 0; t < 16; t++) {
        int buf = t & 1;
        if (t < 15) load_tile(buf ^ 1, (t + 1) * 32);
        if (t < 15) asm volatile("cp.async.wait_group 1;");
        else        asm volatile("cp.async.wait_group 0;");
        __syncthreads();

        const __nv_bfloat16* sAh = smem + (buf * 4 + 0) * TILE_E;
        const __nv_bfloat16* sAl = smem + (buf * 4 + 1) * TILE_E;
        const __nv_bfloat16* sBh = smem + (buf * 4 + 2) * TILE_E;
        const __nv_bfloat16* sBl = smem + (buf * 4 + 3) * TILE_E;

#pragma unroll
        for (int ks = 0; ks < 2; ks++) {
            unsigned bhf[4][2], blf[4][2];
#pragma unroll
            for (int nt = 0; nt < 4; nt++) {
                int n = wn * 32 + nt * 8 + (lane & 7);
                int k = ks * 16 + ((lane >> 3) & 1) * 8;
                ldmat_x2(bhf[nt], smem_u32(sBh + n * ASTR + k));
                ldmat_x2(blf[nt], smem_u32(sBl + n * ASTR + k));
            }
#pragma unroll
            for (int mt = 0; mt < 4; mt++) {
                int m = wm * 64 + mt * 16 + ((lane >> 3) & 1) * 8 + (lane & 7);
                int k = ks * 16 + ((lane >> 4) & 1) * 8;
                unsigned ahf[4], alf[4];
                ldmat_x4(ahf, smem_u32(sAh + m * ASTR + k));
                ldmat_x4(alf, smem_u32(sAl + m * ASTR + k));
#pragma unroll
                for (int nt = 0; nt < 4; nt++) {
                    mma16816(acc[mt][nt], ahf, bhf[nt]);
                    mma16816(acc[mt][nt], ahf, blf[nt]);
                    mma16816(acc[mt][nt], alf, bhf[nt]);
                }
            }
        }
        __syncthreads();
    }

    const int g  = lane >> 2;
    const int t4 = lane & 3;
#pragma unroll
    for (int mt = 0; mt < 4; mt++) {
#pragma unroll
        for (int nt = 0; nt < 4; nt++) {
            int row = bm + wm * 64 + mt * 16 + g;
            int col = bn + wn * 32 + nt * 8 + 2 * t4;
            float2 bv = *(const float2*)&bias[col];
            float2 o0 = make_float2(acc[mt][nt][0] + bv.x, acc[mt][nt][1] + bv.y);
            float2 o1 = make_float2(acc[mt][nt][2] + bv.x, acc[mt][nt][3] + bv.y);
            *(float2*)&C[(size_t)row * 512 + col] = o0;
            *(float2*)&C[(size_t)(row + 8) * 512 + col] = o1;
        }
    }
}

// ---------------- small-M GEMM (MLP tail), 4 rows per thread ----------------
__global__ void gemm_small_kernel(
    const float* __restrict__ A, int lda,
    const float* __restrict__ W,
    const float* __restrict__ bias,
    float* __restrict__ C, int M, int Nc, int K)
{
    int n = blockIdx.x * blockDim.x + threadIdx.x;
    int m0 = blockIdx.y * 4;
    if (n >= Nc || m0 >= M) return;
    const float* a0 = A + (size_t)m0 * lda;
    const float* a1 = a0 + lda;
    const float* a2 = a1 + lda;
    const float* a3 = a2 + lda;
    float s0 = 0.f, s1 = 0.f, s2 = 0.f, s3 = 0.f;
    for (int k = 0; k < K; k++) {
        float w = W[(size_t)k * Nc + n];
        s0 += a0[k] * w; s1 += a1[k] * w; s2 += a2[k] * w; s3 += a3[k] * w;
    }
    float bv = bias[n];
    C[(size_t)(m0 + 0) * Nc + n] = s0 + bv;
    C[(size_t)(m0 + 1) * Nc + n] = s1 + bv;
    C[(size_t)(m0 + 2) * Nc + n] = s2 + bv;
    C[(size_t)(m0 + 3) * Nc + n] = s3 + bv;
}

// ---------------- fused GATv2 layer, single pass, float4 gathers ------------
// mode 0: out = gelu(gat + bias)      -> out[NV*512]
// mode 1: out = add_time(gat + bias)  -> out[NV*513]
__global__ void __launch_bounds__(128) gat_kernel(
    const float* __restrict__ xl, const float* __restrict__ xr,
    const float* __restrict__ att, const float* __restrict__ bias,
    float* __restrict__ out, int mode)
{
    int dst = blockIdx.x;
    int w = threadIdx.x >> 5;
    int l = threadIdx.x & 31;
    int start = g_off[dst];
    int end   = g_off[dst + 1];

    float4 xrr  = ((const float4*)(xr  + (size_t)dst * HC + w * CC))[l];
    float4 attr = ((const float4*)(att + w * CC))[l];

    float mx = -1e30f, den = 0.f;
    float4 acc = make_float4(0.f, 0.f, 0.f, 0.f);

    for (int j = start; j < end; j++) {
        int s = g_srcv[j];
        float4 xv = ((const float4*)(xl + (size_t)s * HC + w * CC))[l];
        float v0 = xv.x + xrr.x; v0 = (v0 > 0.f) ? v0 : 0.2f * v0;
        float v1 = xv.y + xrr.y; v1 = (v1 > 0.f) ? v1 : 0.2f * v1;
        float v2 = xv.z + xrr.z; v2 = (v2 > 0.f) ? v2 : 0.2f * v2;
        float v3 = xv.w + xrr.w; v3 = (v3 > 0.f) ? v3 : 0.2f * v3;
        float a = v0 * attr.x + v1 * attr.y + v2 * attr.z + v3 * attr.w;
#pragma unroll
        for (int o = 16; o; o >>= 1) a += __shfl_xor_sync(0xffffffffu, a, o);
        float nm = fmaxf(mx, a);
        float sc = __expf(mx - nm);
        float ew = __expf(a - nm);
        den = den * sc + ew;
        acc.x = acc.x * sc + ew * xv.x;
        acc.y = acc.y * sc + ew * xv.y;
        acc.z = acc.z * sc + ew * xv.z;
        acc.w = acc.w * sc + ew * xv.w;
        mx = nm;
    }

    float inv = 1.0f / (den + 1e-16f);
    float4 bv = ((const float4*)(bias + w * CC))[l];
    float v[4];
    v[0] = acc.x * inv + bv.x;
    v[1] = acc.y * inv + bv.y;
    v[2] = acc.z * inv + bv.z;
    v[3] = acc.w * inv + bv.w;

    if (mode == 0) {
        float4 o;
        o.x = 0.5f * v[0] * (1.0f + erff(v[0] * 0.70710678118654752f));
        o.y = 0.5f * v[1] * (1.0f + erff(v[1] * 0.70710678118654752f));
        o.z = 0.5f * v[2] * (1.0f + erff(v[2] * 0.70710678118654752f));
        o.w = 0.5f * v[3] * (1.0f + erff(v[3] * 0.70710678118654752f));
        ((float4*)(out + (size_t)dst * HC + w * CC))[l] = o;
    } else {
        float sq = v[0] * v[0] + v[1] * v[1] + v[2] * v[2] + v[3] * v[3];
#pragma unroll
        for (int o = 16; o; o >>= 1) sq += __shfl_xor_sync(0xffffffffu, sq, o);
        __shared__ float red[4];
        if (l == 0) red[w] = sq;
        __syncthreads();
        float tot = red[0] + red[1] + red[2] + red[3];
        if (threadIdx.x == 0) out[(size_t)dst * D1] = sqrtf(1.0f + tot);
        float* op = out + (size_t)dst * D1 + 1 + w * CC + 4 * l;
        op[0] = v[0]; op[1] = v[1]; op[2] = v[2]; op[3] = v[3];
    }
}

// ---------------- centroid per batch ----------------
__global__ void __launch_bounds__(256) centroid_kernel(
    const float* __restrict__ h3, float* __restrict__ gm)
{
    int b = blockIdx.x;
    __shared__ float avg[D1];
    const float* basep = h3 + (size_t)b * 128 * D1;
    for (int c = threadIdx.x; c < D1; c += blockDim.x) {
        float s = 0.f;
        for (int r = 0; r < 128; r++) s += basep[(size_t)r * D1 + c];
        avg[c] = s * (1.0f / 128.0f);
    }
    __syncthreads();
    float loc = 0.f;
    for (int c = threadIdx.x; c < D1; c += blockDim.x) {
        float a = avg[c];
        loc += (c == 0) ? -a * a : a * a;
    }
#pragma unroll
    for (int o = 16; o; o >>= 1) loc += __shfl_xor_sync(0xffffffffu, loc, o);
    __shared__ float red[8];
    int w = threadIdx.x >> 5, l = threadIdx.x & 31;
    if (l == 0) red[w] = loc;
    __syncthreads();
    __shared__ float s_invden;
    if (threadIdx.x == 0) {
        float inner = 0.f;
        for (int i = 0; i < 8; i++) inner += red[i];
        s_invden = 1.0f / sqrtf(fmaxf(-inner, 1e-8f));
    }
    __syncthreads();
    float invd = s_invden;
    for (int c = threadIdx.x; c < D1; c += blockDim.x)
        gm[(size_t)b * D1 + c] = avg[c] * invd;
}

// ---------------- llin epilogue (after z@W+b) ----------------
__global__ void __launch_bounds__(256) llin_post_kernel(
    const float* __restrict__ zin, float* __restrict__ zout,
    const float* __restrict__ sptr, int D)
{
    int b = blockIdx.x;
    const float* row = zin + (size_t)b * D;
    float loc = 0.f;
    for (int c = 1 + threadIdx.x; c < D; c += blockDim.x) { float v = row[c]; loc += v * v; }
#pragma unroll
    for (int o = 16; o; o >>= 1) loc += __shfl_xor_sync(0xffffffffu, loc, o);
    __shared__ float red[8];
    int w = threadIdx.x >> 5, l = threadIdx.x & 31;
    if (l == 0) red[w] = loc;
    __syncthreads();
    __shared__ float s_t, s_scale;
    if (threadIdx.x == 0) {
        float sq = 0.f;
        for (int i = 0; i < 8; i++) sq += red[i];
        sq = fmaxf(sq, 1e-8f);
        float z0 = row[0];
        float t = (1.0f / (1.0f + expf(-z0))) * expf(*sptr) + 1.1f;
        s_t = t;
        s_scale = sqrtf((t * t - 1.0f) / sq);
    }
    __syncthreads();
    if (threadIdx.x == 0) zout[(size_t)b * D] = s_t;
    float sc = s_scale;
    for (int c = 1 + threadIdx.x; c < D; c += blockDim.x)
        zout[(size_t)b * D + c] = row[c] * sc;
}

// ---------------- gelu + add_time over z[:,1:] ----------------
__global__ void __launch_bounds__(256) gelu_addtime_kernel(
    const float* __restrict__ zin, float* __restrict__ zout, int D)
{
    int b = blockIdx.x;
    const float* row = zin + (size_t)b * D;
    float* orow = zout + (size_t)b * D;
    float loc = 0.f;
    for (int c = 1 + threadIdx.x; c < D; c += blockDim.x) {
        float x = row[c];
        float g = 0.5f * x * (1.0f + erff(x * 0.70710678118654752f));
        orow[c] = g;
        loc += g * g;
    }
#pragma unroll
    for (int o = 16; o; o >>= 1) loc += __shfl_xor_sync(0xffffffffu, loc, o);
    __shared__ float red[8];
    int w = threadIdx.x >> 5, l = threadIdx.x & 31;
    if (l == 0) red[w] = loc;
    __syncthreads();
    if (threadIdx.x == 0) {
        float tot = 0.f;
        for (int i = 0; i < 8; i++) tot += red[i];
        orow[0] = sqrtf(1.0f + tot);
    }
}

// ---------------- launch ----------------
extern "C" void kernel_launch(void* const* d_in, const int* in_sizes, int n_in,
                              void* d_out, int out_size)
{
    const float* x  = (const float*)d_in[0];
    const int*   ei = (const int*)d_in[1];
    int base = 2;
    if (n_in > 2 && in_sizes[2] == 1) base = 3;   // batch_size scalar present

    const float* Wl1   = (const float*)d_in[base + 0];
    const float* bl1   = (const float*)d_in[base + 1];
    const float* Wr1   = (const float*)d_in[base + 2];
    const float* br1   = (const float*)d_in[base + 3];
    const float* att1  = (const float*)d_in[base + 4];
    const float* bias1 = (const float*)d_in[base + 5];
    const float* Wl2   = (const float*)d_in[base + 6];
    const float* bl2   = (const float*)d_in[base + 7];
    const float* Wr2   = (const float*)d_in[base + 8];
    const float* br2   = (const float*)d_in[base + 9];
    const float* att2  = (const float*)d_in[base + 10];
    const float* bias2 = (const float*)d_in[base + 11];
    const float* Wa    = (const float*)d_in[base + 12];
    const float* ba    = (const float*)d_in[base + 13];
    const float* sa    = (const float*)d_in[base + 14];
    const float* Wb    = (const float*)d_in[base + 15];
    const float* bb    = (const float*)d_in[base + 16];
    const float* sb    = (const float*)d_in[base + 17];
    const float* Wf    = (const float*)d_in[base + 18];
    const float* bf    = (const float*)d_in[base + 19];
    const float* sf    = (const float*)d_in[base + 20];

    float* out = (float*)d_out;

    void* p;
    cudaGetSymbolAddress(&p, g_xl); float* pxl = (float*)p;
    cudaGetSymbolAddress(&p, g_xr); float* pxr = (float*)p;
    cudaGetSymbolAddress(&p, g_h2); float* ph2 = (float*)p;
    cudaGetSymbolAddress(&p, g_h3); float* ph3 = (float*)p;
    cudaGetSymbolAddress(&p, g_za); float* pza = (float*)p;
    cudaGetSymbolAddress(&p, g_z1); float* pz1 = (float*)p;
    cudaGetSymbolAddress(&p, g_z2); float* pz2 = (float*)p;
    cudaGetSymbolAddress(&p, g_zb); float* pzb = (float*)p;
    cudaGetSymbolAddress(&p, g_z3); float* pz3 = (float*)p;
    cudaGetSymbolAddress(&p, g_zf); float* pzf = (float*)p;
    cudaGetSymbolAddress(&p, g_Ah);  __nv_bfloat16* pAh  = (__nv_bfloat16*)p;
    cudaGetSymbolAddress(&p, g_Al);  __nv_bfloat16* pAl  = (__nv_bfloat16*)p;
    cudaGetSymbolAddress(&p, g_Wth); __nv_bfloat16* pWth = (__nv_bfloat16*)p;
    cudaGetSymbolAddress(&p, g_Wtl); __nv_bfloat16* pWtl = (__nv_bfloat16*)p;

    static bool attr_set = false;
    if (!attr_set) {
        cudaFuncSetAttribute(gemm_bf16x3_kernel,
                             cudaFuncAttributeMaxDynamicSharedMemorySize, GEMM_SMEM);
        attr_set = true;
    }

    // CSR build
    zero_deg_kernel<<<(NV + 255) / 256, 256>>>();
    hist_kernel<<<(ETOT + 255) / 256, 256>>>(ei);
    scan_kernel<<<1, 1024>>>();
    scatter_kernel<<<(ETOT + 255) / 256, 256>>>(ei);

    dim3 gb(4, 128);          // (N/128, M/128)
    dim3 gw(16, 16);          // W transpose tiles
    dim3 bw(32, 8);
    int  saN = (NV * 128 + 255) / 256;

    // ---- layer 1 ----
    splitA_kernel<<<saN, 256>>>(x + 1, D1, pAh, pAl);
    splitWT_kernel<<<gw, bw>>>(Wl1, pWth, pWtl);
    gemm_bf16x3_kernel<<<gb, 256, GEMM_SMEM>>>(pAh, pAl, pWth, pWtl, bl1, pxl);
    splitWT_kernel<<<gw, bw>>>(Wr1, pWth, pWtl);
    gemm_bf16x3_kernel<<<gb, 256, GEMM_SMEM>>>(pAh, pAl, pWth, pWtl, br1, pxr);
    gat_kernel<<<NV, 128>>>(pxl, pxr, att1, bias1, ph2, 0);

    // ---- layer 2 ----
    splitA_kernel<<<saN, 256>>>(ph2, HC, pAh, pAl);
    splitWT_kernel<<<gw, bw>>>(Wl2, pWth, pWtl);
    gemm_bf16x3_kernel<<<gb, 256, GEMM_SMEM>>>(pAh, pAl, pWth, pWtl, bl2, pxl);
    splitWT_kernel<<<gw, bw>>>(Wr2, pWth, pWtl);
    gemm_bf16x3_kernel<<<gb, 256, GEMM_SMEM>>>(pAh, pAl, pWth, pWtl, br2, pxr);
    gat_kernel<<<NV, 128>>>(pxl, pxr, att2, bias2, ph3, 1);

    // centroid -> second half of output
    centroid_kernel<<<BB, 256>>>(ph3, out + (size_t)BB * D1);

    // MLP head on z = hb[:,0,:] = h3 rows with stride 128*513
    gemm_small_kernel<<<dim3((DA + 255) / 256, BB / 4), 256>>>(ph3, 128 * D1, Wa, ba, pza, BB, DA, D1);
    llin_post_kernel<<<BB, 256>>>(pza, pz1, sa, DA);
    gelu_addtime_kernel<<<BB, 256>>>(pz1, pz2, DA);
    gemm_small_kernel<<<dim3((D1 + 255) / 256, BB / 4), 256>>>(pz2, DA, Wb, bb, pzb, BB, D1, DA);
    llin_post_kernel<<<BB, 256>>>(pzb, pz3, sb, D1);
    gemm_small_kernel<<<dim3((D1 + 255) / 256, BB / 4), 256>>>(pz3, D1, Wf, bf, pzf, BB, D1, D1);
    llin_post_kernel<<<BB, 256>>>(pzf, out, sf, D1);

    (void)out_size;
}

// round 7
// speedup vs baseline: 2.3324x; 1.1700x over previous
#include <cuda_runtime.h>
#include <cuda_fp16.h>
#include <stdint.h>
#include <math.h>

// ---------------- problem constants ----------------
constexpr int NV   = 16384;
constexpr int EDG  = 131072;
constexpr int ETOT = EDG + NV;
constexpr int HC   = 512;
constexpr int CC   = 128;
constexpr int D1   = 513;
constexpr int BB   = 128;
constexpr int DA   = 2049;

// ---------------- device scratch ----------------
__device__ float g_xl[NV * HC];
__device__ float g_xr[NV * HC];
__device__ float g_h2[NV * HC];
__device__ float g_h3[NV * D1];
__device__ int   g_deg[NV];
__device__ int   g_off[NV + 1];
__device__ int   g_cur[NV];
__device__ int   g_srcv[ETOT];
__device__ float g_za[BB * DA];
__device__ float g_z1[BB * DA];
__device__ float g_z2[BB * DA];
__device__ float g_zb[BB * D1];
__device__ float g_z3[BB * D1];
__device__ float g_zf[BB * D1];
__device__ __half g_A16h[NV * HC];
__device__ __half g_A16l[NV * HC];
__device__ __half g_W1t[HC * HC];    // Wl^T fp16 [n][k]
__device__ __half g_W2t[HC * HC];    // Wr^T fp16 [n][k]

// ---------------- CSR build ----------------
__global__ void zero_deg_kernel() {
    int i = blockIdx.x * blockDim.x + threadIdx.x;
    if (i < NV) g_deg[i] = 0;
}

__global__ void hist_kernel(const int* __restrict__ ei) {
    int i = blockIdx.x * blockDim.x + threadIdx.x;
    if (i >= ETOT) return;
    int dst = (i < EDG) ? ei[EDG + i] : (i - EDG);
    atomicAdd(&g_deg[dst], 1);
}

__global__ void scan_kernel() {
    __shared__ int part[1024];
    int t = threadIdx.x;
    int loc[16];
    int s = 0;
#pragma unroll
    for (int i = 0; i < 16; i++) { loc[i] = s; s += g_deg[t * 16 + i]; }
    part[t] = s;
    __syncthreads();
    for (int d = 1; d < 1024; d <<= 1) {
        int v = (t >= d) ? part[t - d] : 0;
        __syncthreads();
        part[t] += v;
        __syncthreads();
    }
    int base = (t > 0) ? part[t - 1] : 0;
#pragma unroll
    for (int i = 0; i < 16; i++) {
        int o = base + loc[i];
        g_off[t * 16 + i] = o;
        g_cur[t * 16 + i] = o;
    }
    if (t == 1023) g_off[NV] = part[1023];
}

__global__ void scatter_kernel(const int* __restrict__ ei) {
    int i = blockIdx.x * blockDim.x + threadIdx.x;
    if (i >= ETOT) return;
    int s, d;
    if (i < EDG) { s = ei[i]; d = ei[EDG + i]; }
    else         { s = d = i - EDG; }
    int p = atomicAdd(&g_cur[d], 1);
    g_srcv[p] = s;
}

// ---------------- helpers ----------------
__device__ __forceinline__ void ldmat_x4(unsigned (&r)[4], unsigned addr) {
    asm volatile("ldmatrix.sync.aligned.m8n8.x4.shared.b16 {%0,%1,%2,%3}, [%4];"
        : "=r"(r[0]), "=r"(r[1]), "=r"(r[2]), "=r"(r[3]) : "r"(addr));
}
__device__ __forceinline__ void ldmat_x2(unsigned (&r)[2], unsigned addr) {
    asm volatile("ldmatrix.sync.aligned.m8n8.x2.shared.b16 {%0,%1}, [%2];"
        : "=r"(r[0]), "=r"(r[1]) : "r"(addr));
}
__device__ __forceinline__ void mma16816h(float (&d)[4], const unsigned (&a)[4], const unsigned (&b)[2]) {
    asm volatile("mma.sync.aligned.m16n8k16.row.col.f32.f16.f16.f32 "
        "{%0,%1,%2,%3},{%4,%5,%6,%7},{%8,%9},{%0,%1,%2,%3};"
        : "+f"(d[0]), "+f"(d[1]), "+f"(d[2]), "+f"(d[3])
        : "r"(a[0]), "r"(a[1]), "r"(a[2]), "r"(a[3]), "r"(b[0]), "r"(b[1]));
}
__device__ __forceinline__ unsigned smem_u32(const void* p) {
    return (unsigned)__cvta_generic_to_shared(p);
}
__device__ __forceinline__ void cp16(unsigned saddr, const void* g) {
    asm volatile("cp.async.cg.shared.global [%0], [%1], 16;" :: "r"(saddr), "l"(g));
}

// ---------------- pre-split kernels (fp16) ----------------
// A[M,512] fp32 (lda) -> Ah/Al fp16 dense
__global__ void splitA_kernel(const float* __restrict__ A, int lda,
                              __half* __restrict__ Ah, __half* __restrict__ Al) {
    int i = blockIdx.x * blockDim.x + threadIdx.x;
    if (i >= NV * 128) return;
    int row = i >> 7, c4 = (i & 127) * 4;
    const float* ap = A + (size_t)row * lda + c4;
    float v0 = ap[0], v1 = ap[1], v2 = ap[2], v3 = ap[3];
    __half h0 = __float2half_rn(v0), h1 = __float2half_rn(v1);
    __half h2 = __float2half_rn(v2), h3 = __float2half_rn(v3);
    __half2 H0 = {h0, h1}, H1 = {h2, h3};
    __half2 L0 = {__float2half_rn(v0 - __half2float(h0)),
                  __float2half_rn(v1 - __half2float(h1))};
    __half2 L1 = {__float2half_rn(v2 - __half2float(h2)),
                  __float2half_rn(v3 - __half2float(h3))};
    size_t o = (size_t)row * 512 + c4;
    *(uint2*)&Ah[o] = make_uint2(*(unsigned*)&H0, *(unsigned*)&H1);
    *(uint2*)&Al[o] = make_uint2(*(unsigned*)&L0, *(unsigned*)&L1);
}

// W[512,512] k-major fp32 -> W^T fp16 [n][k]
__global__ void splitWT_kernel(const float* __restrict__ W, __half* __restrict__ T) {
    __shared__ float t[32][33];
    int bn = blockIdx.x * 32, bk = blockIdx.y * 32;
    int tx = threadIdx.x, ty = threadIdx.y;
#pragma unroll
    for (int i = 0; i < 4; i++) {
        int k = bk + ty + i * 8;
        t[ty + i * 8][tx] = W[(size_t)k * 512 + bn + tx];
    }
    __syncthreads();
#pragma unroll
    for (int i = 0; i < 4; i++) {
        int n = bn + ty + i * 8;
        T[(size_t)n * 512 + bk + tx] = __float2half_rn(t[tx][ty + i * 8]);
    }
}

// ---------------- fused dual GEMM (fp16 split-x2) ----------------
// blockIdx.x < 4 : C1[.,bn] = A @ W1 + b1 ; else C2 with W2/b2
// CTA tile 128x128, BK=32, double buffered cp.async, 8 warps x (64x32)
constexpr int ASTR    = 40;                    // halfs per smem row (32 data + 8 pad)
constexpr int TILE_E  = 128 * ASTR;            // 5120 halfs = 10240 B
constexpr int GEMM_SMEM = 2 * 3 * TILE_E * 2;  // 61440 B

__global__ void __launch_bounds__(256, 2) gemm_dual_kernel(
    const __half* __restrict__ Ah, const __half* __restrict__ Al,
    const __half* __restrict__ W1, const __half* __restrict__ W2,
    const float* __restrict__ b1, const float* __restrict__ b2,
    float* __restrict__ C1, float* __restrict__ C2)
{
    extern __shared__ __half smem[];
    const int tid  = threadIdx.x;
    const int lane = tid & 31;
    const int warp = tid >> 5;
    const int wm   = warp >> 2;
    const int wn   = warp & 3;
    const int bm   = blockIdx.y * 128;
    const bool second = (blockIdx.x >= 4);
    const int bn   = (blockIdx.x & 3) * 128;

    const __half* Wt  = second ? W2 : W1;
    const float* bias = second ? b2 : b1;
    float* C          = second ? C2 : C1;

    const __half* gsrc[3] = { Ah + (size_t)bm * 512, Al + (size_t)bm * 512,
                              Wt + (size_t)bn * 512 };

    float acc[4][4][4];
#pragma unroll
    for (int mt = 0; mt < 4; mt++)
#pragma unroll
        for (int nt = 0; nt < 4; nt++)
#pragma unroll
            for (int q = 0; q < 4; q++) acc[mt][nt][q] = 0.f;

    // per tile: 3 arrays x 512 16B-chunks = 1536 / 256 threads = 6 each
    auto load_tile = [&](int buf, int k0) {
#pragma unroll
        for (int i = 0; i < 6; i++) {
            int id  = tid + i * 256;
            int arr = id >> 9;
            int w   = id & 511;
            int r   = w >> 2;
            int c16 = w & 3;
            __half* s = smem + (buf * 3 + arr) * TILE_E;
            cp16(smem_u32(s + r * ASTR + c16 * 8),
                 gsrc[arr] + (size_t)r * 512 + k0 + c16 * 8);
        }
        asm volatile("cp.async.commit_group;");
    };

    load_tile(0, 0);

    for (int t = 0; t < 16; t++) {
        int buf = t & 1;
        if (t < 15) load_tile(buf ^ 1, (t + 1) * 32);
        if (t < 15) asm volatile("cp.async.wait_group 1;");
        else        asm volatile("cp.async.wait_group 0;");
        __syncthreads();

        const __half* sAh = smem + (buf * 3 + 0) * TILE_E;
        const __half* sAl = smem + (buf * 3 + 1) * TILE_E;
        const __half* sB  = smem + (buf * 3 + 2) * TILE_E;

#pragma unroll
        for (int ks = 0; ks < 2; ks++) {
            unsigned bf[4][2];
#pragma unroll
            for (int nt = 0; nt < 4; nt++) {
                int n = wn * 32 + nt * 8 + (lane & 7);
                int k = ks * 16 + ((lane >> 3) & 1) * 8;
                ldmat_x2(bf[nt], smem_u32(sB + n * ASTR + k));
            }
#pragma unroll
            for (int mt = 0; mt < 4; mt++) {
                int m = wm * 64 + mt * 16 + ((lane >> 3) & 1) * 8 + (lane & 7);
                int k = ks * 16 + ((lane >> 4) & 1) * 8;
                unsigned ahf[4], alf[4];
                ldmat_x4(ahf, smem_u32(sAh + m * ASTR + k));
                ldmat_x4(alf, smem_u32(sAl + m * ASTR + k));
#pragma unroll
                for (int nt = 0; nt < 4; nt++) {
                    mma16816h(acc[mt][nt], ahf, bf[nt]);
                    mma16816h(acc[mt][nt], alf, bf[nt]);
                }
            }
        }
        __syncthreads();
    }

    const int g  = lane >> 2;
    const int t4 = lane & 3;
#pragma unroll
    for (int mt = 0; mt < 4; mt++) {
#pragma unroll
        for (int nt = 0; nt < 4; nt++) {
            int row = bm + wm * 64 + mt * 16 + g;
            int col = bn + wn * 32 + nt * 8 + 2 * t4;
            float2 bv = *(const float2*)&bias[col];
            float2 o0 = make_float2(acc[mt][nt][0] + bv.x, acc[mt][nt][1] + bv.y);
            float2 o1 = make_float2(acc[mt][nt][2] + bv.x, acc[mt][nt][3] + bv.y);
            *(float2*)&C[(size_t)row * 512 + col] = o0;
            *(float2*)&C[(size_t)(row + 8) * 512 + col] = o1;
        }
    }
}

// ---------------- small-M GEMM (MLP tail) ----------------
__global__ void gemm_small_kernel(
    const float* __restrict__ A, int lda,
    const float* __restrict__ W,
    const float* __restrict__ bias,
    float* __restrict__ C, int M, int Nc, int K)
{
    int n = blockIdx.x * blockDim.x + threadIdx.x;
    int m0 = blockIdx.y * 4;
    if (n >= Nc || m0 >= M) return;
    const float* a0 = A + (size_t)m0 * lda;
    const float* a1 = a0 + lda;
    const float* a2 = a1 + lda;
    const float* a3 = a2 + lda;
    float s0 = 0.f, s1 = 0.f, s2 = 0.f, s3 = 0.f;
    for (int k = 0; k < K; k++) {
        float w = W[(size_t)k * Nc + n];
        s0 += a0[k] * w; s1 += a1[k] * w; s2 += a2[k] * w; s3 += a3[k] * w;
    }
    float bv = bias[n];
    C[(size_t)(m0 + 0) * Nc + n] = s0 + bv;
    C[(size_t)(m0 + 1) * Nc + n] = s1 + bv;
    C[(size_t)(m0 + 2) * Nc + n] = s2 + bv;
    C[(size_t)(m0 + 3) * Nc + n] = s3 + bv;
}

// ---------------- fused GATv2 layer, single pass, float4 gathers ------------
__global__ void __launch_bounds__(128) gat_kernel(
    const float* __restrict__ xl, const float* __restrict__ xr,
    const float* __restrict__ att, const float* __restrict__ bias,
    float* __restrict__ out, int mode)
{
    int dst = blockIdx.x;
    int w = threadIdx.x >> 5;
    int l = threadIdx.x & 31;
    int start = g_off[dst];
    int end   = g_off[dst + 1];

    float4 xrr  = ((const float4*)(xr  + (size_t)dst * HC + w * CC))[l];
    float4 attr = ((const float4*)(att + w * CC))[l];

    float mx = -1e30f, den = 0.f;
    float4 acc = make_float4(0.f, 0.f, 0.f, 0.f);

    for (int j = start; j < end; j++) {
        int s = g_srcv[j];
        float4 xv = ((const float4*)(xl + (size_t)s * HC + w * CC))[l];
        float v0 = xv.x + xrr.x; v0 = (v0 > 0.f) ? v0 : 0.2f * v0;
        float v1 = xv.y + xrr.y; v1 = (v1 > 0.f) ? v1 : 0.2f * v1;
        float v2 = xv.z + xrr.z; v2 = (v2 > 0.f) ? v2 : 0.2f * v2;
        float v3 = xv.w + xrr.w; v3 = (v3 > 0.f) ? v3 : 0.2f * v3;
        float a = v0 * attr.x + v1 * attr.y + v2 * attr.z + v3 * attr.w;
#pragma unroll
        for (int o = 16; o; o >>= 1) a += __shfl_xor_sync(0xffffffffu, a, o);
        float nm = fmaxf(mx, a);
        float sc = __expf(mx - nm);
        float ew = __expf(a - nm);
        den = den * sc + ew;
        acc.x = acc.x * sc + ew * xv.x;
        acc.y = acc.y * sc + ew * xv.y;
        acc.z = acc.z * sc + ew * xv.z;
        acc.w = acc.w * sc + ew * xv.w;
        mx = nm;
    }

    float inv = 1.0f / (den + 1e-16f);
    float4 bv = ((const float4*)(bias + w * CC))[l];
    float v[4];
    v[0] = acc.x * inv + bv.x;
    v[1] = acc.y * inv + bv.y;
    v[2] = acc.z * inv + bv.z;
    v[3] = acc.w * inv + bv.w;

    if (mode == 0) {
        float4 o;
        o.x = 0.5f * v[0] * (1.0f + erff(v[0] * 0.70710678118654752f));
        o.y = 0.5f * v[1] * (1.0f + erff(v[1] * 0.70710678118654752f));
        o.z = 0.5f * v[2] * (1.0f + erff(v[2] * 0.70710678118654752f));
        o.w = 0.5f * v[3] * (1.0f + erff(v[3] * 0.70710678118654752f));
        ((float4*)(out + (size_t)dst * HC + w * CC))[l] = o;
    } else {
        float sq = v[0] * v[0] + v[1] * v[1] + v[2] * v[2] + v[3] * v[3];
#pragma unroll
        for (int o = 16; o; o >>= 1) sq += __shfl_xor_sync(0xffffffffu, sq, o);
        __shared__ float red[4];
        if (l == 0) red[w] = sq;
        __syncthreads();
        float tot = red[0] + red[1] + red[2] + red[3];
        if (threadIdx.x == 0) out[(size_t)dst * D1] = sqrtf(1.0f + tot);
        float* op = out + (size_t)dst * D1 + 1 + w * CC + 4 * l;
        op[0] = v[0]; op[1] = v[1]; op[2] = v[2]; op[3] = v[3];
    }
}

// ---------------- centroid per batch ----------------
__global__ void __launch_bounds__(256) centroid_kernel(
    const float* __restrict__ h3, float* __restrict__ gm)
{
    int b = blockIdx.x;
    __shared__ float avg[D1];
    const float* basep = h3 + (size_t)b * 128 * D1;
    for (int c = threadIdx.x; c < D1; c += blockDim.x) {
        float s = 0.f;
        for (int r = 0; r < 128; r++) s += basep[(size_t)r * D1 + c];
        avg[c] = s * (1.0f / 128.0f);
    }
    __syncthreads();
    float loc = 0.f;
    for (int c = threadIdx.x; c < D1; c += blockDim.x) {
        float a = avg[c];
        loc += (c == 0) ? -a * a : a * a;
    }
#pragma unroll
    for (int o = 16; o; o >>= 1) loc += __shfl_xor_sync(0xffffffffu, loc, o);
    __shared__ float red[8];
    int w = threadIdx.x >> 5, l = threadIdx.x & 31;
    if (l == 0) red[w] = loc;
    __syncthreads();
    __shared__ float s_invden;
    if (threadIdx.x == 0) {
        float inner = 0.f;
        for (int i = 0; i < 8; i++) inner += red[i];
        s_invden = 1.0f / sqrtf(fmaxf(-inner, 1e-8f));
    }
    __syncthreads();
    float invd = s_invden;
    for (int c = threadIdx.x; c < D1; c += blockDim.x)
        gm[(size_t)b * D1 + c] = avg[c] * invd;
}

// ---------------- llin epilogue ----------------
__global__ void __launch_bounds__(256) llin_post_kernel(
    const float* __restrict__ zin, float* __restrict__ zout,
    const float* __restrict__ sptr, int D)
{
    int b = blockIdx.x;
    const float* row = zin + (size_t)b * D;
    float loc = 0.f;
    for (int c = 1 + threadIdx.x; c < D; c += blockDim.x) { float v = row[c]; loc += v * v; }
#pragma unroll
    for (int o = 16; o; o >>= 1) loc += __shfl_xor_sync(0xffffffffu, loc, o);
    __shared__ float red[8];
    int w = threadIdx.x >> 5, l = threadIdx.x & 31;
    if (l == 0) red[w] = loc;
    __syncthreads();
    __shared__ float s_t, s_scale;
    if (threadIdx.x == 0) {
        float sq = 0.f;
        for (int i = 0; i < 8; i++) sq += red[i];
        sq = fmaxf(sq, 1e-8f);
        float z0 = row[0];
        float t = (1.0f / (1.0f + expf(-z0))) * expf(*sptr) + 1.1f;
        s_t = t;
        s_scale = sqrtf((t * t - 1.0f) / sq);
    }
    __syncthreads();
    if (threadIdx.x == 0) zout[(size_t)b * D] = s_t;
    float sc = s_scale;
    for (int c = 1 + threadIdx.x; c < D; c += blockDim.x)
        zout[(size_t)b * D + c] = row[c] * sc;
}

// ---------------- gelu + add_time ----------------
__global__ void __launch_bounds__(256) gelu_addtime_kernel(
    const float* __restrict__ zin, float* __restrict__ zout, int D)
{
    int b = blockIdx.x;
    const float* row = zin + (size_t)b * D;
    float* orow = zout + (size_t)b * D;
    float loc = 0.f;
    for (int c = 1 + threadIdx.x; c < D; c += blockDim.x) {
        float x = row[c];
        float g = 0.5f * x * (1.0f + erff(x * 0.70710678118654752f));
        orow[c] = g;
        loc += g * g;
    }
#pragma unroll
    for (int o = 16; o; o >>= 1) loc += __shfl_xor_sync(0xffffffffu, loc, o);
    __shared__ float red[8];
    int w = threadIdx.x >> 5, l = threadIdx.x & 31;
    if (l == 0) red[w] = loc;
    __syncthreads();
    if (threadIdx.x == 0) {
        float tot = 0.f;
        for (int i = 0; i < 8; i++) tot += red[i];
        orow[0] = sqrtf(1.0f + tot);
    }
}

// ---------------- launch ----------------
extern "C" void kernel_launch(void* const* d_in, const int* in_sizes, int n_in,
                              void* d_out, int out_size)
{
    const float* x  = (const float*)d_in[0];
    const int*   ei = (const int*)d_in[1];
    int base = 2;
    if (n_in > 2 && in_sizes[2] == 1) base = 3;

    const float* Wl1   = (const float*)d_in[base + 0];
    const float* bl1   = (const float*)d_in[base + 1];
    const float* Wr1   = (const float*)d_in[base + 2];
    const float* br1   = (const float*)d_in[base + 3];
    const float* att1  = (const float*)d_in[base + 4];
    const float* bias1 = (const float*)d_in[base + 5];
    const float* Wl2   = (const float*)d_in[base + 6];
    const float* bl2   = (const float*)d_in[base + 7];
    const float* Wr2   = (const float*)d_in[base + 8];
    const float* br2   = (const float*)d_in[base + 9];
    const float* att2  = (const float*)d_in[base + 10];
    const float* bias2 = (const float*)d_in[base + 11];
    const float* Wa    = (const float*)d_in[base + 12];
    const float* ba    = (const float*)d_in[base + 13];
    const float* sa    = (const float*)d_in[base + 14];
    const float* Wb    = (const float*)d_in[base + 15];
    const float* bb    = (const float*)d_in[base + 16];
    const float* sb    = (const float*)d_in[base + 17];
    const float* Wf    = (const float*)d_in[base + 18];
    const float* bf    = (const float*)d_in[base + 19];
    const float* sf    = (const float*)d_in[base + 20];

    float* out = (float*)d_out;

    void* p;
    cudaGetSymbolAddress(&p, g_xl); float* pxl = (float*)p;
    cudaGetSymbolAddress(&p, g_xr); float* pxr = (float*)p;
    cudaGetSymbolAddress(&p, g_h2); float* ph2 = (float*)p;
    cudaGetSymbolAddress(&p, g_h3); float* ph3 = (float*)p;
    cudaGetSymbolAddress(&p, g_za); float* pza = (float*)p;
    cudaGetSymbolAddress(&p, g_z1); float* pz1 = (float*)p;
    cudaGetSymbolAddress(&p, g_z2); float* pz2 = (float*)p;
    cudaGetSymbolAddress(&p, g_zb); float* pzb = (float*)p;
    cudaGetSymbolAddress(&p, g_z3); float* pz3 = (float*)p;
    cudaGetSymbolAddress(&p, g_zf); float* pzf = (float*)p;
    cudaGetSymbolAddress(&p, g_A16h); __half* pAh = (__half*)p;
    cudaGetSymbolAddress(&p, g_A16l); __half* pAl = (__half*)p;
    cudaGetSymbolAddress(&p, g_W1t);  __half* pW1 = (__half*)p;
    cudaGetSymbolAddress(&p, g_W2t);  __half* pW2 = (__half*)p;

    static bool attr_set = false;
    if (!attr_set) {
        cudaFuncSetAttribute(gemm_dual_kernel,
                             cudaFuncAttributeMaxDynamicSharedMemorySize, GEMM_SMEM);
        attr_set = true;
    }

    // CSR build
    zero_deg_kernel<<<(NV + 255) / 256, 256>>>();
    hist_kernel<<<(ETOT + 255) / 256, 256>>>(ei);
    scan_kernel<<<1, 1024>>>();
    scatter_kernel<<<(ETOT + 255) / 256, 256>>>(ei);

    dim3 gb(8, 128);          // fused: 2 GEMMs x (4 col-blocks) x 128 row-blocks
    dim3 gw(16, 16);
    dim3 bw(32, 8);
    int  saN = (NV * 128 + 255) / 256;

    // ---- layer 1 ----
    splitA_kernel<<<saN, 256>>>(x + 1, D1, pAh, pAl);
    splitWT_kernel<<<gw, bw>>>(Wl1, pW1);
    splitWT_kernel<<<gw, bw>>>(Wr1, pW2);
    gemm_dual_kernel<<<gb, 256, GEMM_SMEM>>>(pAh, pAl, pW1, pW2, bl1, br1, pxl, pxr);
    gat_kernel<<<NV, 128>>>(pxl, pxr, att1, bias1, ph2, 0);

    // ---- layer 2 ----
    splitA_kernel<<<saN, 256>>>(ph2, HC, pAh, pAl);
    splitWT_kernel<<<gw, bw>>>(Wl2, pW1);
    splitWT_kernel<<<gw, bw>>>(Wr2, pW2);
    gemm_dual_kernel<<<gb, 256, GEMM_SMEM>>>(pAh, pAl, pW1, pW2, bl2, br2, pxl, pxr);
    gat_kernel<<<NV, 128>>>(pxl, pxr, att2, bias2, ph3, 1);

    // centroid -> second half of output
    centroid_kernel<<<BB, 256>>>(ph3, out + (size_t)BB * D1);

    // MLP head
    gemm_small_kernel<<<dim3((DA + 255) / 256, BB / 4), 256>>>(ph3, 128 * D1, Wa, ba, pza, BB, DA, D1);
    llin_post_kernel<<<BB, 256>>>(pza, pz1, sa, DA);
    gelu_addtime_kernel<<<BB, 256>>>(pz1, pz2, DA);
    gemm_small_kernel<<<dim3((D1 + 255) / 256, BB / 4), 256>>>(pz2, DA, Wb, bb, pzb, BB, D1, DA);
    llin_post_kernel<<<BB, 256>>>(pzb, pz3, sb, D1);
    gemm_small_kernel<<<dim3((D1 + 255) / 256, BB / 4), 256>>>(pz3, D1, Wf, bf, pzf, BB, D1, D1);
    llin_post_kernel<<<BB, 256>>>(pzf, out, sf, D1);

    (void)out_size;
}

// round 8
// speedup vs baseline: 2.4297x; 1.0417x over previous
#include <cuda_runtime.h>
#include <cuda_fp16.h>
#include <stdint.h>
#include <math.h>

// ---------------- problem constants ----------------
constexpr int NV   = 16384;
constexpr int EDG  = 131072;
constexpr int ETOT = EDG + NV;
constexpr int HC   = 512;
constexpr int CC   = 128;
constexpr int D1   = 513;
constexpr int BB   = 128;
constexpr int DA   = 2049;

// ---------------- device scratch ----------------
__device__ float g_xl[NV * HC];
__device__ float g_xr[NV * HC];
__device__ float g_h2[NV * HC];
__device__ float g_h3[NV * D1];
__device__ int   g_deg[NV];
__device__ int   g_off[NV + 1];
__device__ int   g_cur[NV];
__device__ int   g_srcv[ETOT];
__device__ float g_za[BB * DA];
__device__ float g_z1[BB * DA];
__device__ float g_z2[BB * DA];
__device__ float g_zb[BB * D1];
__device__ float g_z3[BB * D1];
__device__ float g_zf[BB * D1];
__device__ __half g_A16[NV * HC];
__device__ __half g_W1t[HC * HC];    // Wl^T fp16 [n][k]
__device__ __half g_W2t[HC * HC];    // Wr^T fp16 [n][k]

// ---------------- CSR build ----------------
__global__ void zero_deg_kernel() {
    int i = blockIdx.x * blockDim.x + threadIdx.x;
    if (i < NV) g_deg[i] = 0;
}

__global__ void hist_kernel(const int* __restrict__ ei) {
    int i = blockIdx.x * blockDim.x + threadIdx.x;
    if (i >= ETOT) return;
    int dst = (i < EDG) ? ei[EDG + i] : (i - EDG);
    atomicAdd(&g_deg[dst], 1);
}

__global__ void scan_kernel() {
    __shared__ int part[1024];
    int t = threadIdx.x;
    int loc[16];
    int s = 0;
#pragma unroll
    for (int i = 0; i < 16; i++) { loc[i] = s; s += g_deg[t * 16 + i]; }
    part[t] = s;
    __syncthreads();
    for (int d = 1; d < 1024; d <<= 1) {
        int v = (t >= d) ? part[t - d] : 0;
        __syncthreads();
        part[t] += v;
        __syncthreads();
    }
    int base = (t > 0) ? part[t - 1] : 0;
#pragma unroll
    for (int i = 0; i < 16; i++) {
        int o = base + loc[i];
        g_off[t * 16 + i] = o;
        g_cur[t * 16 + i] = o;
    }
    if (t == 1023) g_off[NV] = part[1023];
}

__global__ void scatter_kernel(const int* __restrict__ ei) {
    int i = blockIdx.x * blockDim.x + threadIdx.x;
    if (i >= ETOT) return;
    int s, d;
    if (i < EDG) { s = ei[i]; d = ei[EDG + i]; }
    else         { s = d = i - EDG; }
    int p = atomicAdd(&g_cur[d], 1);
    g_srcv[p] = s;
}

// ---------------- helpers ----------------
__device__ __forceinline__ void ldmat_x4(unsigned (&r)[4], unsigned addr) {
    asm volatile("ldmatrix.sync.aligned.m8n8.x4.shared.b16 {%0,%1,%2,%3}, [%4];"
        : "=r"(r[0]), "=r"(r[1]), "=r"(r[2]), "=r"(r[3]) : "r"(addr));
}
__device__ __forceinline__ void ldmat_x2(unsigned (&r)[2], unsigned addr) {
    asm volatile("ldmatrix.sync.aligned.m8n8.x2.shared.b16 {%0,%1}, [%2];"
        : "=r"(r[0]), "=r"(r[1]) : "r"(addr));
}
__device__ __forceinline__ void mma16816h(float (&d)[4], const unsigned (&a)[4], const unsigned (&b)[2]) {
    asm volatile("mma.sync.aligned.m16n8k16.row.col.f32.f16.f16.f32 "
        "{%0,%1,%2,%3},{%4,%5,%6,%7},{%8,%9},{%0,%1,%2,%3};"
        : "+f"(d[0]), "+f"(d[1]), "+f"(d[2]), "+f"(d[3])
        : "r"(a[0]), "r"(a[1]), "r"(a[2]), "r"(a[3]), "r"(b[0]), "r"(b[1]));
}
__device__ __forceinline__ unsigned smem_u32(const void* p) {
    return (unsigned)__cvta_generic_to_shared(p);
}
__device__ __forceinline__ void cp16(unsigned saddr, const void* g) {
    asm volatile("cp.async.cg.shared.global [%0], [%1], 16;" :: "r"(saddr), "l"(g));
}

// ---------------- conversion kernels (fp16) ----------------
// A[M,512] fp32 (lda) -> fp16 dense
__global__ void convA_kernel(const float* __restrict__ A, int lda,
                             __half* __restrict__ Ah) {
    int i = blockIdx.x * blockDim.x + threadIdx.x;
    if (i >= NV * 128) return;
    int row = i >> 7, c4 = (i & 127) * 4;
    const float* ap = A + (size_t)row * lda + c4;
    __half2 H0 = {__float2half_rn(ap[0]), __float2half_rn(ap[1])};
    __half2 H1 = {__float2half_rn(ap[2]), __float2half_rn(ap[3])};
    *(uint2*)&Ah[(size_t)row * 512 + c4] = make_uint2(*(unsigned*)&H0, *(unsigned*)&H1);
}

// W[512,512] k-major fp32 -> W^T fp16 [n][k]
__global__ void splitWT_kernel(const float* __restrict__ W, __half* __restrict__ T) {
    __shared__ float t[32][33];
    int bn = blockIdx.x * 32, bk = blockIdx.y * 32;
    int tx = threadIdx.x, ty = threadIdx.y;
#pragma unroll
    for (int i = 0; i < 4; i++) {
        int k = bk + ty + i * 8;
        t[ty + i * 8][tx] = W[(size_t)k * 512 + bn + tx];
    }
    __syncthreads();
#pragma unroll
    for (int i = 0; i < 4; i++) {
        int n = bn + ty + i * 8;
        T[(size_t)n * 512 + bk + tx] = __float2half_rn(t[tx][ty + i * 8]);
    }
}

// ---------------- fused dual GEMM (plain fp16, fp32 accum) ----------------
// blockIdx.x < 4 : C1[.,bn] = A @ W1 + b1 ; else C2 with W2/b2
constexpr int ASTR    = 40;                    // halfs per smem row (32 data + 8 pad)
constexpr int TILE_E  = 128 * ASTR;            // 5120 halfs = 10240 B
constexpr int GEMM_SMEM = 2 * 2 * TILE_E * 2;  // 40960 B

__global__ void __launch_bounds__(256, 2) gemm_dual_kernel(
    const __half* __restrict__ Ah,
    const __half* __restrict__ W1, const __half* __restrict__ W2,
    const float* __restrict__ b1, const float* __restrict__ b2,
    float* __restrict__ C1, float* __restrict__ C2)
{
    extern __shared__ __half smem[];
    const int tid  = threadIdx.x;
    const int lane = tid & 31;
    const int warp = tid >> 5;
    const int wm   = warp >> 2;
    const int wn   = warp & 3;
    const int bm   = blockIdx.y * 128;
    const bool second = (blockIdx.x >= 4);
    const int bn   = (blockIdx.x & 3) * 128;

    const __half* Wt  = second ? W2 : W1;
    const float* bias = second ? b2 : b1;
    float* C          = second ? C2 : C1;

    const __half* gsrc[2] = { Ah + (size_t)bm * 512, Wt + (size_t)bn * 512 };

    float acc[4][4][4];
#pragma unroll
    for (int mt = 0; mt < 4; mt++)
#pragma unroll
        for (int nt = 0; nt < 4; nt++)
#pragma unroll
            for (int q = 0; q < 4; q++) acc[mt][nt][q] = 0.f;

    // per tile: 2 arrays x 512 16B-chunks = 1024 / 256 threads = 4 each
    auto load_tile = [&](int buf, int k0) {
#pragma unroll
        for (int i = 0; i < 4; i++) {
            int id  = tid + i * 256;
            int arr = id >> 9;
            int w   = id & 511;
            int r   = w >> 2;
            int c16 = w & 3;
            __half* s = smem + (buf * 2 + arr) * TILE_E;
            cp16(smem_u32(s + r * ASTR + c16 * 8),
                 gsrc[arr] + (size_t)r * 512 + k0 + c16 * 8);
        }
        asm volatile("cp.async.commit_group;");
    };

    load_tile(0, 0);

    for (int t = 0; t < 16; t++) {
        int buf = t & 1;
        if (t < 15) load_tile(buf ^ 1, (t + 1) * 32);
        if (t < 15) asm volatile("cp.async.wait_group 1;");
        else        asm volatile("cp.async.wait_group 0;");
        __syncthreads();

        const __half* sA = smem + (buf * 2 + 0) * TILE_E;
        const __half* sB = smem + (buf * 2 + 1) * TILE_E;

#pragma unroll
        for (int ks = 0; ks < 2; ks++) {
            unsigned bf[4][2];
#pragma unroll
            for (int nt = 0; nt < 4; nt++) {
                int n = wn * 32 + nt * 8 + (lane & 7);
                int k = ks * 16 + ((lane >> 3) & 1) * 8;
                ldmat_x2(bf[nt], smem_u32(sB + n * ASTR + k));
            }
#pragma unroll
            for (int mt = 0; mt < 4; mt++) {
                int m = wm * 64 + mt * 16 + ((lane >> 3) & 1) * 8 + (lane & 7);
                int k = ks * 16 + ((lane >> 4) & 1) * 8;
                unsigned af[4];
                ldmat_x4(af, smem_u32(sA + m * ASTR + k));
#pragma unroll
                for (int nt = 0; nt < 4; nt++)
                    mma16816h(acc[mt][nt], af, bf[nt]);
            }
        }
        __syncthreads();
    }

    const int g  = lane >> 2;
    const int t4 = lane & 3;
#pragma unroll
    for (int mt = 0; mt < 4; mt++) {
#pragma unroll
        for (int nt = 0; nt < 4; nt++) {
            int row = bm + wm * 64 + mt * 16 + g;
            int col = bn + wn * 32 + nt * 8 + 2 * t4;
            float2 bv = *(const float2*)&bias[col];
            float2 o0 = make_float2(acc[mt][nt][0] + bv.x, acc[mt][nt][1] + bv.y);
            float2 o1 = make_float2(acc[mt][nt][2] + bv.x, acc[mt][nt][3] + bv.y);
            *(float2*)&C[(size_t)row * 512 + col] = o0;
            *(float2*)&C[(size_t)(row + 8) * 512 + col] = o1;
        }
    }
}

// ---------------- small-M GEMM (MLP tail) ----------------
__global__ void gemm_small_kernel(
    const float* __restrict__ A, int lda,
    const float* __restrict__ W,
    const float* __restrict__ bias,
    float* __restrict__ C, int M, int Nc, int K)
{
    int n = blockIdx.x * blockDim.x + threadIdx.x;
    int m0 = blockIdx.y * 4;
    if (n >= Nc || m0 >= M) return;
    const float* a0 = A + (size_t)m0 * lda;
    const float* a1 = a0 + lda;
    const float* a2 = a1 + lda;
    const float* a3 = a2 + lda;
    float s0 = 0.f, s1 = 0.f, s2 = 0.f, s3 = 0.f;
    for (int k = 0; k < K; k++) {
        float w = W[(size_t)k * Nc + n];
        s0 += a0[k] * w; s1 += a1[k] * w; s2 += a2[k] * w; s3 += a3[k] * w;
    }
    float bv = bias[n];
    C[(size_t)(m0 + 0) * Nc + n] = s0 + bv;
    C[(size_t)(m0 + 1) * Nc + n] = s1 + bv;
    C[(size_t)(m0 + 2) * Nc + n] = s2 + bv;
    C[(size_t)(m0 + 3) * Nc + n] = s3 + bv;
}

// ---------------- fused GATv2 layer, 2-stream online softmax ------------
__global__ void __launch_bounds__(128) gat_kernel(
    const float* __restrict__ xl, const float* __restrict__ xr,
    const float* __restrict__ att, const float* __restrict__ bias,
    float* __restrict__ out, int mode)
{
    int dst = blockIdx.x;
    int w = threadIdx.x >> 5;
    int l = threadIdx.x & 31;
    int start = g_off[dst];
    int end   = g_off[dst + 1];

    float4 xrr  = ((const float4*)(xr  + (size_t)dst * HC + w * CC))[l];
    float4 attr = ((const float4*)(att + w * CC))[l];

    float mx0 = -1e30f, den0 = 0.f;
    float4 a0 = make_float4(0.f, 0.f, 0.f, 0.f);
    float mx1 = -1e30f, den1 = 0.f;
    float4 a1 = make_float4(0.f, 0.f, 0.f, 0.f);

    for (int j = start; j < end; j += 2) {
        // stream 0
        {
            int s = g_srcv[j];
            float4 xv = ((const float4*)(xl + (size_t)s * HC + w * CC))[l];
            float v0 = xv.x + xrr.x; v0 = (v0 > 0.f) ? v0 : 0.2f * v0;
            float v1 = xv.y + xrr.y; v1 = (v1 > 0.f) ? v1 : 0.2f * v1;
            float v2 = xv.z + xrr.z; v2 = (v2 > 0.f) ? v2 : 0.2f * v2;
            float v3 = xv.w + xrr.w; v3 = (v3 > 0.f) ? v3 : 0.2f * v3;
            float a = v0 * attr.x + v1 * attr.y + v2 * attr.z + v3 * attr.w;
#pragma unroll
            for (int o = 16; o; o >>= 1) a += __shfl_xor_sync(0xffffffffu, a, o);
            float nm = fmaxf(mx0, a);
            float sc = __expf(mx0 - nm);
            float ew = __expf(a - nm);
            den0 = den0 * sc + ew;
            a0.x = a0.x * sc + ew * xv.x;
            a0.y = a0.y * sc + ew * xv.y;
            a0.z = a0.z * sc + ew * xv.z;
            a0.w = a0.w * sc + ew * xv.w;
            mx0 = nm;
        }
        // stream 1
        if (j + 1 < end) {
            int s = g_srcv[j + 1];
            float4 xv = ((const float4*)(xl + (size_t)s * HC + w * CC))[l];
            float v0 = xv.x + xrr.x; v0 = (v0 > 0.f) ? v0 : 0.2f * v0;
            float v1 = xv.y + xrr.y; v1 = (v1 > 0.f) ? v1 : 0.2f * v1;
            float v2 = xv.z + xrr.z; v2 = (v2 > 0.f) ? v2 : 0.2f * v2;
            float v3 = xv.w + xrr.w; v3 = (v3 > 0.f) ? v3 : 0.2f * v3;
            float a = v0 * attr.x + v1 * attr.y + v2 * attr.z + v3 * attr.w;
#pragma unroll
            for (int o = 16; o; o >>= 1) a += __shfl_xor_sync(0xffffffffu, a, o);
            float nm = fmaxf(mx1, a);
            float sc = __expf(mx1 - nm);
            float ew = __expf(a - nm);
            den1 = den1 * sc + ew;
            a1.x = a1.x * sc + ew * xv.x;
            a1.y = a1.y * sc + ew * xv.y;
            a1.z = a1.z * sc + ew * xv.z;
            a1.w = a1.w * sc + ew * xv.w;
            mx1 = nm;
        }
    }

    // merge streams
    float nm = fmaxf(mx0, mx1);
    float s0 = __expf(mx0 - nm), s1 = __expf(mx1 - nm);
    float den = den0 * s0 + den1 * s1;
    float4 acc;
    acc.x = a0.x * s0 + a1.x * s1;
    acc.y = a0.y * s0 + a1.y * s1;
    acc.z = a0.z * s0 + a1.z * s1;
    acc.w = a0.w * s0 + a1.w * s1;

    float inv = 1.0f / (den + 1e-16f);
    float4 bv = ((const float4*)(bias + w * CC))[l];
    float v[4];
    v[0] = acc.x * inv + bv.x;
    v[1] = acc.y * inv + bv.y;
    v[2] = acc.z * inv + bv.z;
    v[3] = acc.w * inv + bv.w;

    if (mode == 0) {
        float4 o;
        o.x = 0.5f * v[0] * (1.0f + erff(v[0] * 0.70710678118654752f));
        o.y = 0.5f * v[1] * (1.0f + erff(v[1] * 0.70710678118654752f));
        o.z = 0.5f * v[2] * (1.0f + erff(v[2] * 0.70710678118654752f));
        o.w = 0.5f * v[3] * (1.0f + erff(v[3] * 0.70710678118654752f));
        ((float4*)(out + (size_t)dst * HC + w * CC))[l] = o;
    } else {
        float sq = v[0] * v[0] + v[1] * v[1] + v[2] * v[2] + v[3] * v[3];
#pragma unroll
        for (int o = 16; o; o >>= 1) sq += __shfl_xor_sync(0xffffffffu, sq, o);
        __shared__ float red[4];
        if (l == 0) red[w] = sq;
        __syncthreads();
        float tot = red[0] + red[1] + red[2] + red[3];
        if (threadIdx.x == 0) out[(size_t)dst * D1] = sqrtf(1.0f + tot);
        float* op = out + (size_t)dst * D1 + 1 + w * CC + 4 * l;
        op[0] = v[0]; op[1] = v[1]; op[2] = v[2]; op[3] = v[3];
    }
}

// ---------------- centroid per batch ----------------
__global__ void __launch_bounds__(256) centroid_kernel(
    const float* __restrict__ h3, float* __restrict__ gm)
{
    int b = blockIdx.x;
    __shared__ float avg[D1];
    const float* basep = h3 + (size_t)b * 128 * D1;
    for (int c = threadIdx.x; c < D1; c += blockDim.x) {
        float s = 0.f;
        for (int r = 0; r < 128; r++) s += basep[(size_t)r * D1 + c];
        avg[c] = s * (1.0f / 128.0f);
    }
    __syncthreads();
    float loc = 0.f;
    for (int c = threadIdx.x; c < D1; c += blockDim.x) {
        float a = avg[c];
        loc += (c == 0) ? -a * a : a * a;
    }
#pragma unroll
    for (int o = 16; o; o >>= 1) loc += __shfl_xor_sync(0xffffffffu, loc, o);
    __shared__ float red[8];
    int w = threadIdx.x >> 5, l = threadIdx.x & 31;
    if (l == 0) red[w] = loc;
    __syncthreads();
    __shared__ float s_invden;
    if (threadIdx.x == 0) {
        float inner = 0.f;
        for (int i = 0; i < 8; i++) inner += red[i];
        s_invden = 1.0f / sqrtf(fmaxf(-inner, 1e-8f));
    }
    __syncthreads();
    float invd = s_invden;
    for (int c = threadIdx.x; c < D1; c += blockDim.x)
        gm[(size_t)b * D1 + c] = avg[c] * invd;
}

// ---------------- llin epilogue ----------------
__global__ void __launch_bounds__(256) llin_post_kernel(
    const float* __restrict__ zin, float* __restrict__ zout,
    const float* __restrict__ sptr, int D)
{
    int b = blockIdx.x;
    const float* row = zin + (size_t)b * D;
    float loc = 0.f;
    for (int c = 1 + threadIdx.x; c < D; c += blockDim.x) { float v = row[c]; loc += v * v; }
#pragma unroll
    for (int o = 16; o; o >>= 1) loc += __shfl_xor_sync(0xffffffffu, loc, o);
    __shared__ float red[8];
    int w = threadIdx.x >> 5, l = threadIdx.x & 31;
    if (l == 0) red[w] = loc;
    __syncthreads();
    __shared__ float s_t, s_scale;
    if (threadIdx.x == 0) {
        float sq = 0.f;
        for (int i = 0; i < 8; i++) sq += red[i];
        sq = fmaxf(sq, 1e-8f);
        float z0 = row[0];
        float t = (1.0f / (1.0f + expf(-z0))) * expf(*sptr) + 1.1f;
        s_t = t;
        s_scale = sqrtf((t * t - 1.0f) / sq);
    }
    __syncthreads();
    if (threadIdx.x == 0) zout[(size_t)b * D] = s_t;
    float sc = s_scale;
    for (int c = 1 + threadIdx.x; c < D; c += blockDim.x)
        zout[(size_t)b * D + c] = row[c] * sc;
}

// ---------------- gelu + add_time ----------------
__global__ void __launch_bounds__(256) gelu_addtime_kernel(
    const float* __restrict__ zin, float* __restrict__ zout, int D)
{
    int b = blockIdx.x;
    const float* row = zin + (size_t)b * D;
    float* orow = zout + (size_t)b * D;
    float loc = 0.f;
    for (int c = 1 + threadIdx.x; c < D; c += blockDim.x) {
        float x = row[c];
        float g = 0.5f * x * (1.0f + erff(x * 0.70710678118654752f));
        orow[c] = g;
        loc += g * g;
    }
#pragma unroll
    for (int o = 16; o; o >>= 1) loc += __shfl_xor_sync(0xffffffffu, loc, o);
    __shared__ float red[8];
    int w = threadIdx.x >> 5, l = threadIdx.x & 31;
    if (l == 0) red[w] = loc;
    __syncthreads();
    if (threadIdx.x == 0) {
        float tot = 0.f;
        for (int i = 0; i < 8; i++) tot += red[i];
        orow[0] = sqrtf(1.0f + tot);
    }
}

// ---------------- launch ----------------
extern "C" void kernel_launch(void* const* d_in, const int* in_sizes, int n_in,
                              void* d_out, int out_size)
{
    const float* x  = (const float*)d_in[0];
    const int*   ei = (const int*)d_in[1];
    int base = 2;
    if (n_in > 2 && in_sizes[2] == 1) base = 3;

    const float* Wl1   = (const float*)d_in[base + 0];
    const float* bl1   = (const float*)d_in[base + 1];
    const float* Wr1   = (const float*)d_in[base + 2];
    const float* br1   = (const float*)d_in[base + 3];
    const float* att1  = (const float*)d_in[base + 4];
    const float* bias1 = (const float*)d_in[base + 5];
    const float* Wl2   = (const float*)d_in[base + 6];
    const float* bl2   = (const float*)d_in[base + 7];
    const float* Wr2   = (const float*)d_in[base + 8];
    const float* br2   = (const float*)d_in[base + 9];
    const float* att2  = (const float*)d_in[base + 10];
    const float* bias2 = (const float*)d_in[base + 11];
    const float* Wa    = (const float*)d_in[base + 12];
    const float* ba    = (const float*)d_in[base + 13];
    const float* sa    = (const float*)d_in[base + 14];
    const float* Wb    = (const float*)d_in[base + 15];
    const float* bb    = (const float*)d_in[base + 16];
    const float* sb    = (const float*)d_in[base + 17];
    const float* Wf    = (const float*)d_in[base + 18];
    const float* bf    = (const float*)d_in[base + 19];
    const float* sf    = (const float*)d_in[base + 20];

    float* out = (float*)d_out;

    void* p;
    cudaGetSymbolAddress(&p, g_xl); float* pxl = (float*)p;
    cudaGetSymbolAddress(&p, g_xr); float* pxr = (float*)p;
    cudaGetSymbolAddress(&p, g_h2); float* ph2 = (float*)p;
    cudaGetSymbolAddress(&p, g_h3); float* ph3 = (float*)p;
    cudaGetSymbolAddress(&p, g_za); float* pza = (float*)p;
    cudaGetSymbolAddress(&p, g_z1); float* pz1 = (float*)p;
    cudaGetSymbolAddress(&p, g_z2); float* pz2 = (float*)p;
    cudaGetSymbolAddress(&p, g_zb); float* pzb = (float*)p;
    cudaGetSymbolAddress(&p, g_z3); float* pz3 = (float*)p;
    cudaGetSymbolAddress(&p, g_zf); float* pzf = (float*)p;
    cudaGetSymbolAddress(&p, g_A16); __half* pA  = (__half*)p;
    cudaGetSymbolAddress(&p, g_W1t); __half* pW1 = (__half*)p;
    cudaGetSymbolAddress(&p, g_W2t); __half* pW2 = (__half*)p;

    static bool attr_set = false;
    if (!attr_set) {
        cudaFuncSetAttribute(gemm_dual_kernel,
                             cudaFuncAttributeMaxDynamicSharedMemorySize, GEMM_SMEM);
        attr_set = true;
    }

    // CSR build
    zero_deg_kernel<<<(NV + 255) / 256, 256>>>();
    hist_kernel<<<(ETOT + 255) / 256, 256>>>(ei);
    scan_kernel<<<1, 1024>>>();
    scatter_kernel<<<(ETOT + 255) / 256, 256>>>(ei);

    dim3 gb(8, 128);          // fused: 2 GEMMs x 4 col-blocks x 128 row-blocks
    dim3 gw(16, 16);
    dim3 bw(32, 8);
    int  saN = (NV * 128 + 255) / 256;

    // ---- layer 1 ----
    convA_kernel<<<saN, 256>>>(x + 1, D1, pA);
    splitWT_kernel<<<gw, bw>>>(Wl1, pW1);
    splitWT_kernel<<<gw, bw>>>(Wr1, pW2);
    gemm_dual_kernel<<<gb, 256, GEMM_SMEM>>>(pA, pW1, pW2, bl1, br1, pxl, pxr);
    gat_kernel<<<NV, 128>>>(pxl, pxr, att1, bias1, ph2, 0);

    // ---- layer 2 ----
    convA_kernel<<<saN, 256>>>(ph2, HC, pA);
    splitWT_kernel<<<gw, bw>>>(Wl2, pW1);
    splitWT_kernel<<<gw, bw>>>(Wr2, pW2);
    gemm_dual_kernel<<<gb, 256, GEMM_SMEM>>>(pA, pW1, pW2, bl2, br2, pxl, pxr);
    gat_kernel<<<NV, 128>>>(pxl, pxr, att2, bias2, ph3, 1);

    // centroid -> second half of output
    centroid_kernel<<<BB, 256>>>(ph3, out + (size_t)BB * D1);

    // MLP head
    gemm_small_kernel<<<dim3((DA + 255) / 256, BB / 4), 256>>>(ph3, 128 * D1, Wa, ba, pza, BB, DA, D1);
    llin_post_kernel<<<BB, 256>>>(pza, pz1, sa, DA);
    gelu_addtime_kernel<<<BB, 256>>>(pz1, pz2, DA);
    gemm_small_kernel<<<dim3((D1 + 255) / 256, BB / 4), 256>>>(pz2, DA, Wb, bb, pzb, BB, D1, DA);
    llin_post_kernel<<<BB, 256>>>(pzb, pz3, sb, D1);
    gemm_small_kernel<<<dim3((D1 + 255) / 256, BB / 4), 256>>>(pz3, D1, Wf, bf, pzf, BB, D1, D1);
    llin_post_kernel<<<BB, 256>>>(pzf, out, sf, D1);

    (void)out_size;
}

// round 9
// speedup vs baseline: 2.5496x; 1.0493x over previous
#include <cuda_runtime.h>
#include <cuda_fp16.h>
#include <stdint.h>
#include <math.h>

// ---------------- problem constants ----------------
constexpr int NV   = 16384;
constexpr int EDG  = 131072;
constexpr int ETOT = EDG + NV;
constexpr int HC   = 512;
constexpr int CC   = 128;
constexpr int D1   = 513;
constexpr int BB   = 128;
constexpr int DA   = 2049;

// ---------------- device scratch ----------------
__device__ float g_xl[NV * HC];
__device__ float g_xr[NV * HC];
__device__ float g_h3[NV * D1];
__device__ int   g_deg[NV];
__device__ int   g_off[NV + 1];
__device__ int   g_cur[NV];
__device__ int   g_srcv[ETOT];
__device__ float g_za[BB * DA];
__device__ float g_z1[BB * DA];
__device__ float g_z2[BB * DA];
__device__ float g_zb[BB * D1];
__device__ float g_z3[BB * D1];
__device__ float g_zf[BB * D1];
__device__ __half g_A16[NV * HC];
__device__ __half g_W1t[HC * HC];    // Wl^T fp16 [n][k]
__device__ __half g_W2t[HC * HC];    // Wr^T fp16 [n][k]

// ---------------- CSR build ----------------
__global__ void zero_deg_kernel() {
    int i = blockIdx.x * blockDim.x + threadIdx.x;
    if (i < NV) g_deg[i] = 0;
}

__global__ void hist_kernel(const int* __restrict__ ei) {
    int i = blockIdx.x * blockDim.x + threadIdx.x;
    if (i >= ETOT) return;
    int dst = (i < EDG) ? ei[EDG + i] : (i - EDG);
    atomicAdd(&g_deg[dst], 1);
}

__global__ void scan_kernel() {
    __shared__ int part[1024];
    int t = threadIdx.x;
    int loc[16];
    int s = 0;
#pragma unroll
    for (int i = 0; i < 16; i++) { loc[i] = s; s += g_deg[t * 16 + i]; }
    part[t] = s;
    __syncthreads();
    for (int d = 1; d < 1024; d <<= 1) {
        int v = (t >= d) ? part[t - d] : 0;
        __syncthreads();
        part[t] += v;
        __syncthreads();
    }
    int base = (t > 0) ? part[t - 1] : 0;
#pragma unroll
    for (int i = 0; i < 16; i++) {
        int o = base + loc[i];
        g_off[t * 16 + i] = o;
        g_cur[t * 16 + i] = o;
    }
    if (t == 1023) g_off[NV] = part[1023];
}

__global__ void scatter_kernel(const int* __restrict__ ei) {
    int i = blockIdx.x * blockDim.x + threadIdx.x;
    if (i >= ETOT) return;
    int s, d;
    if (i < EDG) { s = ei[i]; d = ei[EDG + i]; }
    else         { s = d = i - EDG; }
    int p = atomicAdd(&g_cur[d], 1);
    g_srcv[p] = s;
}

// ---------------- helpers ----------------
__device__ __forceinline__ void ldmat_x4(unsigned (&r)[4], unsigned addr) {
    asm volatile("ldmatrix.sync.aligned.m8n8.x4.shared.b16 {%0,%1,%2,%3}, [%4];"
        : "=r"(r[0]), "=r"(r[1]), "=r"(r[2]), "=r"(r[3]) : "r"(addr));
}
__device__ __forceinline__ void ldmat_x2(unsigned (&r)[2], unsigned addr) {
    asm volatile("ldmatrix.sync.aligned.m8n8.x2.shared.b16 {%0,%1}, [%2];"
        : "=r"(r[0]), "=r"(r[1]) : "r"(addr));
}
__device__ __forceinline__ void mma16816h(float (&d)[4], const unsigned (&a)[4], const unsigned (&b)[2]) {
    asm volatile("mma.sync.aligned.m16n8k16.row.col.f32.f16.f16.f32 "
        "{%0,%1,%2,%3},{%4,%5,%6,%7},{%8,%9},{%0,%1,%2,%3};"
        : "+f"(d[0]), "+f"(d[1]), "+f"(d[2]), "+f"(d[3])
        : "r"(a[0]), "r"(a[1]), "r"(a[2]), "r"(a[3]), "r"(b[0]), "r"(b[1]));
}
__device__ __forceinline__ unsigned smem_u32(const void* p) {
    return (unsigned)__cvta_generic_to_shared(p);
}
__device__ __forceinline__ void cp16(unsigned saddr, const void* g) {
    asm volatile("cp.async.cg.shared.global [%0], [%1], 16;" :: "r"(saddr), "l"(g));
}

// ---------------- conversion kernels (fp16) ----------------
__global__ void convA_kernel(const float* __restrict__ A, int lda,
                             __half* __restrict__ Ah) {
    int i = blockIdx.x * blockDim.x + threadIdx.x;
    if (i >= NV * 128) return;
    int row = i >> 7, c4 = (i & 127) * 4;
    const float* ap = A + (size_t)row * lda + c4;
    __half2 H0 = {__float2half_rn(ap[0]), __float2half_rn(ap[1])};
    __half2 H1 = {__float2half_rn(ap[2]), __float2half_rn(ap[3])};
    *(uint2*)&Ah[(size_t)row * 512 + c4] = make_uint2(*(unsigned*)&H0, *(unsigned*)&H1);
}

__global__ void splitWT_kernel(const float* __restrict__ W, __half* __restrict__ T) {
    __shared__ float t[32][33];
    int bn = blockIdx.x * 32, bk = blockIdx.y * 32;
    int tx = threadIdx.x, ty = threadIdx.y;
#pragma unroll
    for (int i = 0; i < 4; i++) {
        int k = bk + ty + i * 8;
        t[ty + i * 8][tx] = W[(size_t)k * 512 + bn + tx];
    }
    __syncthreads();
#pragma unroll
    for (int i = 0; i < 4; i++) {
        int n = bn + ty + i * 8;
        T[(size_t)n * 512 + bk + tx] = __float2half_rn(t[tx][ty + i * 8]);
    }
}

// ---------------- fused dual GEMM (fp16, fp32 accum), BK=64 ----------------
constexpr int ASTR    = 72;                    // halfs per smem row (64 data + 8 pad)
constexpr int TILE_E  = 128 * ASTR;            // 9216 halfs = 18432 B
constexpr int GEMM_SMEM = 2 * 2 * TILE_E * 2;  // 73728 B

__global__ void __launch_bounds__(256, 2) gemm_dual_kernel(
    const __half* __restrict__ Ah,
    const __half* __restrict__ W1, const __half* __restrict__ W2,
    const float* __restrict__ b1, const float* __restrict__ b2,
    float* __restrict__ C1, float* __restrict__ C2)
{
    extern __shared__ __half smem[];
    const int tid  = threadIdx.x;
    const int lane = tid & 31;
    const int warp = tid >> 5;
    const int wm   = warp >> 2;
    const int wn   = warp & 3;
    const int bm   = blockIdx.y * 128;
    const bool second = (blockIdx.x >= 4);
    const int bn   = (blockIdx.x & 3) * 128;

    const __half* Wt  = second ? W2 : W1;
    const float* bias = second ? b2 : b1;
    float* C          = second ? C2 : C1;

    const __half* gsrc[2] = { Ah + (size_t)bm * 512, Wt + (size_t)bn * 512 };

    float acc[4][4][4];
#pragma unroll
    for (int mt = 0; mt < 4; mt++)
#pragma unroll
        for (int nt = 0; nt < 4; nt++)
#pragma unroll
            for (int q = 0; q < 4; q++) acc[mt][nt][q] = 0.f;

    // per tile: 2 arrays x 1024 16B-chunks = 2048 / 256 threads = 8 each
    auto load_tile = [&](int buf, int k0) {
#pragma unroll
        for (int i = 0; i < 8; i++) {
            int id  = tid + i * 256;
            int arr = id >> 10;
            int w   = id & 1023;
            int r   = w >> 3;
            int c16 = w & 7;
            __half* s = smem + (buf * 2 + arr) * TILE_E;
            cp16(smem_u32(s + r * ASTR + c16 * 8),
                 gsrc[arr] + (size_t)r * 512 + k0 + c16 * 8);
        }
        asm volatile("cp.async.commit_group;");
    };

    load_tile(0, 0);

    for (int t = 0; t < 8; t++) {
        int buf = t & 1;
        if (t < 7) load_tile(buf ^ 1, (t + 1) * 64);
        if (t < 7) asm volatile("cp.async.wait_group 1;");
        else       asm volatile("cp.async.wait_group 0;");
        __syncthreads();

        const __half* sA = smem + (buf * 2 + 0) * TILE_E;
        const __half* sB = smem + (buf * 2 + 1) * TILE_E;

#pragma unroll
        for (int ks = 0; ks < 4; ks++) {
            unsigned bf[4][2];
#pragma unroll
            for (int nt = 0; nt < 4; nt++) {
                int n = wn * 32 + nt * 8 + (lane & 7);
                int k = ks * 16 + ((lane >> 3) & 1) * 8;
                ldmat_x2(bf[nt], smem_u32(sB + n * ASTR + k));
            }
#pragma unroll
            for (int mt = 0; mt < 4; mt++) {
                int m = wm * 64 + mt * 16 + ((lane >> 3) & 1) * 8 + (lane & 7);
                int k = ks * 16 + ((lane >> 4) & 1) * 8;
                unsigned af[4];
                ldmat_x4(af, smem_u32(sA + m * ASTR + k));
#pragma unroll
                for (int nt = 0; nt < 4; nt++)
                    mma16816h(acc[mt][nt], af, bf[nt]);
            }
        }
        __syncthreads();
    }

    const int g  = lane >> 2;
    const int t4 = lane & 3;
#pragma unroll
    for (int mt = 0; mt < 4; mt++) {
#pragma unroll
        for (int nt = 0; nt < 4; nt++) {
            int row = bm + wm * 64 + mt * 16 + g;
            int col = bn + wn * 32 + nt * 8 + 2 * t4;
            float2 bv = *(const float2*)&bias[col];
            float2 o0 = make_float2(acc[mt][nt][0] + bv.x, acc[mt][nt][1] + bv.y);
            float2 o1 = make_float2(acc[mt][nt][2] + bv.x, acc[mt][nt][3] + bv.y);
            *(float2*)&C[(size_t)row * 512 + col] = o0;
            *(float2*)&C[(size_t)(row + 8) * 512 + col] = o1;
        }
    }
}

// ---------------- small-M GEMM (MLP tail) ----------------
__global__ void gemm_small_kernel(
    const float* __restrict__ A, int lda,
    const float* __restrict__ W,
    const float* __restrict__ bias,
    float* __restrict__ C, int M, int Nc, int K)
{
    int n = blockIdx.x * blockDim.x + threadIdx.x;
    int m0 = blockIdx.y * 4;
    if (n >= Nc || m0 >= M) return;
    const float* a0 = A + (size_t)m0 * lda;
    const float* a1 = a0 + lda;
    const float* a2 = a1 + lda;
    const float* a3 = a2 + lda;
    float s0 = 0.f, s1 = 0.f, s2 = 0.f, s3 = 0.f;
    for (int k = 0; k < K; k++) {
        float w = W[(size_t)k * Nc + n];
        s0 += a0[k] * w; s1 += a1[k] * w; s2 += a2[k] * w; s3 += a3[k] * w;
    }
    float bv = bias[n];
    C[(size_t)(m0 + 0) * Nc + n] = s0 + bv;
    C[(size_t)(m0 + 1) * Nc + n] = s1 + bv;
    C[(size_t)(m0 + 2) * Nc + n] = s2 + bv;
    C[(size_t)(m0 + 3) * Nc + n] = s3 + bv;
}

// ---------------- fused GATv2 layer ------------
// srcv indices fetched 32-at-a-time per warp (coalesced) and shfl-broadcast.
// mode 0: out16 = fp16(gelu(gat + bias))   (feeds layer-2 GEMM directly)
// mode 1: out   = add_time(gat + bias)
__global__ void __launch_bounds__(128) gat_kernel(
    const float* __restrict__ xl, const float* __restrict__ xr,
    const float* __restrict__ att, const float* __restrict__ bias,
    float* __restrict__ out, __half* __restrict__ out16, int mode)
{
    int dst = blockIdx.x;
    int w = threadIdx.x >> 5;
    int l = threadIdx.x & 31;
    int start = g_off[dst];
    int end   = g_off[dst + 1];

    float4 xrr  = ((const float4*)(xr  + (size_t)dst * HC + w * CC))[l];
    float4 attr = ((const float4*)(att + w * CC))[l];

    float mx0 = -1e30f, den0 = 0.f;
    float4 a0 = make_float4(0.f, 0.f, 0.f, 0.f);
    float mx1 = -1e30f, den1 = 0.f;
    float4 a1 = make_float4(0.f, 0.f, 0.f, 0.f);

    for (int c0 = start; c0 < end; c0 += 32) {
        int myi = c0 + l;
        int mysrc = (myi < end) ? g_srcv[myi] : 0;
        int lim = end - c0; if (lim > 32) lim = 32;
        for (int jj = 0; jj < lim; jj += 2) {
            // stream 0
            {
                int s = __shfl_sync(0xffffffffu, mysrc, jj);
                float4 xv = ((const float4*)(xl + (size_t)s * HC + w * CC))[l];
                float v0 = xv.x + xrr.x; v0 = (v0 > 0.f) ? v0 : 0.2f * v0;
                float v1 = xv.y + xrr.y; v1 = (v1 > 0.f) ? v1 : 0.2f * v1;
                float v2 = xv.z + xrr.z; v2 = (v2 > 0.f) ? v2 : 0.2f * v2;
                float v3 = xv.w + xrr.w; v3 = (v3 > 0.f) ? v3 : 0.2f * v3;
                float a = v0 * attr.x + v1 * attr.y + v2 * attr.z + v3 * attr.w;
#pragma unroll
                for (int o = 16; o; o >>= 1) a += __shfl_xor_sync(0xffffffffu, a, o);
                float nm = fmaxf(mx0, a);
                float sc = __expf(mx0 - nm);
                float ew = __expf(a - nm);
                den0 = den0 * sc + ew;
                a0.x = a0.x * sc + ew * xv.x;
                a0.y = a0.y * sc + ew * xv.y;
                a0.z = a0.z * sc + ew * xv.z;
                a0.w = a0.w * sc + ew * xv.w;
                mx0 = nm;
            }
            // stream 1
            if (jj + 1 < lim) {
                int s = __shfl_sync(0xffffffffu, mysrc, jj + 1);
                float4 xv = ((const float4*)(xl + (size_t)s * HC + w * CC))[l];
                float v0 = xv.x + xrr.x; v0 = (v0 > 0.f) ? v0 : 0.2f * v0;
                float v1 = xv.y + xrr.y; v1 = (v1 > 0.f) ? v1 : 0.2f * v1;
                float v2 = xv.z + xrr.z; v2 = (v2 > 0.f) ? v2 : 0.2f * v2;
                float v3 = xv.w + xrr.w; v3 = (v3 > 0.f) ? v3 : 0.2f * v3;
                float a = v0 * attr.x + v1 * attr.y + v2 * attr.z + v3 * attr.w;
#pragma unroll
                for (int o = 16; o; o >>= 1) a += __shfl_xor_sync(0xffffffffu, a, o);
                float nm = fmaxf(mx1, a);
                float sc = __expf(mx1 - nm);
                float ew = __expf(a - nm);
                den1 = den1 * sc + ew;
                a1.x = a1.x * sc + ew * xv.x;
                a1.y = a1.y * sc + ew * xv.y;
                a1.z = a1.z * sc + ew * xv.z;
                a1.w = a1.w * sc + ew * xv.w;
                mx1 = nm;
            }
        }
    }

    // merge streams
    float nm = fmaxf(mx0, mx1);
    float s0 = __expf(mx0 - nm), s1 = __expf(mx1 - nm);
    float den = den0 * s0 + den1 * s1;
    float4 acc;
    acc.x = a0.x * s0 + a1.x * s1;
    acc.y = a0.y * s0 + a1.y * s1;
    acc.z = a0.z * s0 + a1.z * s1;
    acc.w = a0.w * s0 + a1.w * s1;

    float inv = 1.0f / (den + 1e-16f);
    float4 bv = ((const float4*)(bias + w * CC))[l];
    float v[4];
    v[0] = acc.x * inv + bv.x;
    v[1] = acc.y * inv + bv.y;
    v[2] = acc.z * inv + bv.z;
    v[3] = acc.w * inv + bv.w;

    if (mode == 0) {
        float g0 = 0.5f * v[0] * (1.0f + erff(v[0] * 0.70710678118654752f));
        float g1 = 0.5f * v[1] * (1.0f + erff(v[1] * 0.70710678118654752f));
        float g2 = 0.5f * v[2] * (1.0f + erff(v[2] * 0.70710678118654752f));
        float g3 = 0.5f * v[3] * (1.0f + erff(v[3] * 0.70710678118654752f));
        __half2 H0 = {__float2half_rn(g0), __float2half_rn(g1)};
        __half2 H1 = {__float2half_rn(g2), __float2half_rn(g3)};
        *(uint2*)(out16 + (size_t)dst * HC + w * CC + 4 * l) =
            make_uint2(*(unsigned*)&H0, *(unsigned*)&H1);
    } else {
        float sq = v[0] * v[0] + v[1] * v[1] + v[2] * v[2] + v[3] * v[3];
#pragma unroll
        for (int o = 16; o; o >>= 1) sq += __shfl_xor_sync(0xffffffffu, sq, o);
        __shared__ float red[4];
        if (l == 0) red[w] = sq;
        __syncthreads();
        float tot = red[0] + red[1] + red[2] + red[3];
        if (threadIdx.x == 0) out[(size_t)dst * D1] = sqrtf(1.0f + tot);
        float* op = out + (size_t)dst * D1 + 1 + w * CC + 4 * l;
        op[0] = v[0]; op[1] = v[1]; op[2] = v[2]; op[3] = v[3];
    }
}

// ---------------- centroid per batch ----------------
__global__ void __launch_bounds__(256) centroid_kernel(
    const float* __restrict__ h3, float* __restrict__ gm)
{
    int b = blockIdx.x;
    __shared__ float avg[D1];
    const float* basep = h3 + (size_t)b * 128 * D1;
    for (int c = threadIdx.x; c < D1; c += blockDim.x) {
        float s = 0.f;
        for (int r = 0; r < 128; r++) s += basep[(size_t)r * D1 + c];
        avg[c] = s * (1.0f / 128.0f);
    }
    __syncthreads();
    float loc = 0.f;
    for (int c = threadIdx.x; c < D1; c += blockDim.x) {
        float a = avg[c];
        loc += (c == 0) ? -a * a : a * a;
    }
#pragma unroll
    for (int o = 16; o; o >>= 1) loc += __shfl_xor_sync(0xffffffffu, loc, o);
    __shared__ float red[8];
    int w = threadIdx.x >> 5, l = threadIdx.x & 31;
    if (l == 0) red[w] = loc;
    __syncthreads();
    __shared__ float s_invden;
    if (threadIdx.x == 0) {
        float inner = 0.f;
        for (int i = 0; i < 8; i++) inner += red[i];
        s_invden = 1.0f / sqrtf(fmaxf(-inner, 1e-8f));
    }
    __syncthreads();
    float invd = s_invden;
    for (int c = threadIdx.x; c < D1; c += blockDim.x)
        gm[(size_t)b * D1 + c] = avg[c] * invd;
}

// ---------------- llin epilogue ----------------
__global__ void __launch_bounds__(256) llin_post_kernel(
    const float* __restrict__ zin, float* __restrict__ zout,
    const float* __restrict__ sptr, int D)
{
    int b = blockIdx.x;
    const float* row = zin + (size_t)b * D;
    float loc = 0.f;
    for (int c = 1 + threadIdx.x; c < D; c += blockDim.x) { float v = row[c]; loc += v * v; }
#pragma unroll
    for (int o = 16; o; o >>= 1) loc += __shfl_xor_sync(0xffffffffu, loc, o);
    __shared__ float red[8];
    int w = threadIdx.x >> 5, l = threadIdx.x & 31;
    if (l == 0) red[w] = loc;
    __syncthreads();
    __shared__ float s_t, s_scale;
    if (threadIdx.x == 0) {
        float sq = 0.f;
        for (int i = 0; i < 8; i++) sq += red[i];
        sq = fmaxf(sq, 1e-8f);
        float z0 = row[0];
        float t = (1.0f / (1.0f + expf(-z0))) * expf(*sptr) + 1.1f;
        s_t = t;
        s_scale = sqrtf((t * t - 1.0f) / sq);
    }
    __syncthreads();
    if (threadIdx.x == 0) zout[(size_t)b * D] = s_t;
    float sc = s_scale;
    for (int c = 1 + threadIdx.x; c < D; c += blockDim.x)
        zout[(size_t)b * D + c] = row[c] * sc;
}

// ---------------- gelu + add_time ----------------
__global__ void __launch_bounds__(256) gelu_addtime_kernel(
    const float* __restrict__ zin, float* __restrict__ zout, int D)
{
    int b = blockIdx.x;
    const float* row = zin + (size_t)b * D;
    float* orow = zout + (size_t)b * D;
    float loc = 0.f;
    for (int c = 1 + threadIdx.x; c < D; c += blockDim.x) {
        float x = row[c];
        float g = 0.5f * x * (1.0f + erff(x * 0.70710678118654752f));
        orow[c] = g;
        loc += g * g;
    }
#pragma unroll
    for (int o = 16; o; o >>= 1) loc += __shfl_xor_sync(0xffffffffu, loc, o);
    __shared__ float red[8];
    int w = threadIdx.x >> 5, l = threadIdx.x & 31;
    if (l == 0) red[w] = loc;
    __syncthreads();
    if (threadIdx.x == 0) {
        float tot = 0.f;
        for (int i = 0; i < 8; i++) tot += red[i];
        orow[0] = sqrtf(1.0f + tot);
    }
}

// ---------------- launch ----------------
extern "C" void kernel_launch(void* const* d_in, const int* in_sizes, int n_in,
                              void* d_out, int out_size)
{
    const float* x  = (const float*)d_in[0];
    const int*   ei = (const int*)d_in[1];
    int base = 2;
    if (n_in > 2 && in_sizes[2] == 1) base = 3;

    const float* Wl1   = (const float*)d_in[base + 0];
    const float* bl1   = (const float*)d_in[base + 1];
    const float* Wr1   = (const float*)d_in[base + 2];
    const float* br1   = (const float*)d_in[base + 3];
    const float* att1  = (const float*)d_in[base + 4];
    const float* bias1 = (const float*)d_in[base + 5];
    const float* Wl2   = (const float*)d_in[base + 6];
    const float* bl2   = (const float*)d_in[base + 7];
    const float* Wr2   = (const float*)d_in[base + 8];
    const float* br2   = (const float*)d_in[base + 9];
    const float* att2  = (const float*)d_in[base + 10];
    const float* bias2 = (const float*)d_in[base + 11];
    const float* Wa    = (const float*)d_in[base + 12];
    const float* ba    = (const float*)d_in[base + 13];
    const float* sa    = (const float*)d_in[base + 14];
    const float* Wb    = (const float*)d_in[base + 15];
    const float* bb    = (const float*)d_in[base + 16];
    const float* sb    = (const float*)d_in[base + 17];
    const float* Wf    = (const float*)d_in[base + 18];
    const float* bf    = (const float*)d_in[base + 19];
    const float* sf    = (const float*)d_in[base + 20];

    float* out = (float*)d_out;

    void* p;
    cudaGetSymbolAddress(&p, g_xl); float* pxl = (float*)p;
    cudaGetSymbolAddress(&p, g_xr); float* pxr = (float*)p;
    cudaGetSymbolAddress(&p, g_h3); float* ph3 = (float*)p;
    cudaGetSymbolAddress(&p, g_za); float* pza = (float*)p;
    cudaGetSymbolAddress(&p, g_z1); float* pz1 = (float*)p;
    cudaGetSymbolAddress(&p, g_z2); float* pz2 = (float*)p;
    cudaGetSymbolAddress(&p, g_zb); float* pzb = (float*)p;
    cudaGetSymbolAddress(&p, g_z3); float* pz3 = (float*)p;
    cudaGetSymbolAddress(&p, g_zf); float* pzf = (float*)p;
    cudaGetSymbolAddress(&p, g_A16); __half* pA  = (__half*)p;
    cudaGetSymbolAddress(&p, g_W1t); __half* pW1 = (__half*)p;
    cudaGetSymbolAddress(&p, g_W2t); __half* pW2 = (__half*)p;

    static bool attr_set = false;
    if (!attr_set) {
        cudaFuncSetAttribute(gemm_dual_kernel,
                             cudaFuncAttributeMaxDynamicSharedMemorySize, GEMM_SMEM);
        attr_set = true;
    }

    dim3 gb(8, 128);
    dim3 gw(16, 16);
    dim3 bw(32, 8);
    int  saN = (NV * 128 + 255) / 256;

    // ---- layer 1 GEMM first (4th launch = gemm_dual -> gets ncu-profiled) ----
    convA_kernel<<<saN, 256>>>(x + 1, D1, pA);
    splitWT_kernel<<<gw, bw>>>(Wl1, pW1);
    splitWT_kernel<<<gw, bw>>>(Wr1, pW2);
    gemm_dual_kernel<<<gb, 256, GEMM_SMEM>>>(pA, pW1, pW2, bl1, br1, pxl, pxr);

    // ---- CSR build (independent of layer-1 GEMM) ----
    zero_deg_kernel<<<(NV + 255) / 256, 256>>>();
    hist_kernel<<<(ETOT + 255) / 256, 256>>>(ei);
    scan_kernel<<<1, 1024>>>();
    scatter_kernel<<<(ETOT + 255) / 256, 256>>>(ei);

    // ---- layer 1 GAT (writes fp16 A for layer 2 directly) ----
    gat_kernel<<<NV, 128>>>(pxl, pxr, att1, bias1, nullptr, pA, 0);

    // ---- layer 2 ----
    splitWT_kernel<<<gw, bw>>>(Wl2, pW1);
    splitWT_kernel<<<gw, bw>>>(Wr2, pW2);
    gemm_dual_kernel<<<gb, 256, GEMM_SMEM>>>(pA, pW1, pW2, bl2, br2, pxl, pxr);
    gat_kernel<<<NV, 128>>>(pxl, pxr, att2, bias2, ph3, nullptr, 1);

    // centroid -> second half of output
    centroid_kernel<<<BB, 256>>>(ph3, out + (size_t)BB * D1);

    // MLP head
    gemm_small_kernel<<<dim3((DA + 255) / 256, BB / 4), 256>>>(ph3, 128 * D1, Wa, ba, pza, BB, DA, D1);
    llin_post_kernel<<<BB, 256>>>(pza, pz1, sa, DA);
    gelu_addtime_kernel<<<BB, 256>>>(pz1, pz2, DA);
    gemm_small_kernel<<<dim3((D1 + 255) / 256, BB / 4), 256>>>(pz2, DA, Wb, bb, pzb, BB, D1, DA);
    llin_post_kernel<<<BB, 256>>>(pzb, pz3, sb, D1);
    gemm_small_kernel<<<dim3((D1 + 255) / 256, BB / 4), 256>>>(pz3, D1, Wf, bf, pzf, BB, D1, D1);
    llin_post_kernel<<<BB, 256>>>(pzf, out, sf, D1);

    (void)out_size;
}

// round 11
// speedup vs baseline: 2.5602x; 1.0042x over previous
#include <cuda_runtime.h>
#include <cuda_fp16.h>
#include <stdint.h>
#include <math.h>

// ---------------- problem constants ----------------
constexpr int NV   = 16384;
constexpr int EDG  = 131072;
constexpr int ETOT = EDG + NV;
constexpr int HC   = 512;
constexpr int CC   = 128;
constexpr int D1   = 513;
constexpr int BB   = 128;
constexpr int DA   = 2049;

// ---------------- device scratch ----------------
__device__ float g_xl[NV * HC];
__device__ float g_xr[NV * HC];
__device__ float g_h3[NV * D1];
__device__ int   g_deg[NV];          // zero-initialized; re-zeroed by scan each run
__device__ int   g_off[NV + 1];
__device__ int   g_cur[NV];
__device__ int   g_srcv[ETOT];
__device__ float g_za[BB * DA];
__device__ float g_z1[BB * DA];
__device__ float g_z2[BB * DA];
__device__ float g_zb[BB * D1];
__device__ float g_z3[BB * D1];
__device__ float g_zf[BB * D1];
__device__ __half g_A16[NV * HC];
__device__ __half g_W1t[HC * HC];
__device__ __half g_W2t[HC * HC];

// ---------------- helpers ----------------
__device__ __forceinline__ void ldmat_x4(unsigned (&r)[4], unsigned addr) {
    asm volatile("ldmatrix.sync.aligned.m8n8.x4.shared.b16 {%0,%1,%2,%3}, [%4];"
        : "=r"(r[0]), "=r"(r[1]), "=r"(r[2]), "=r"(r[3]) : "r"(addr));
}
__device__ __forceinline__ void ldmat_x2(unsigned (&r)[2], unsigned addr) {
    asm volatile("ldmatrix.sync.aligned.m8n8.x2.shared.b16 {%0,%1}, [%2];"
        : "=r"(r[0]), "=r"(r[1]) : "r"(addr));
}
__device__ __forceinline__ void mma16816h(float (&d)[4], const unsigned (&a)[4], const unsigned (&b)[2]) {
    asm volatile("mma.sync.aligned.m16n8k16.row.col.f32.f16.f16.f32 "
        "{%0,%1,%2,%3},{%4,%5,%6,%7},{%8,%9},{%0,%1,%2,%3};"
        : "+f"(d[0]), "+f"(d[1]), "+f"(d[2]), "+f"(d[3])
        : "r"(a[0]), "r"(a[1]), "r"(a[2]), "r"(a[3]), "r"(b[0]), "r"(b[1]));
}
__device__ __forceinline__ unsigned smem_u32(const void* p) {
    return (unsigned)__cvta_generic_to_shared(p);
}
__device__ __forceinline__ void cp16(unsigned saddr, const void* g) {
    asm volatile("cp.async.cg.shared.global [%0], [%1], 16;" :: "r"(saddr), "l"(g));
}

// ---------------- shared bodies ----------------
__device__ __forceinline__ void convA_body(int i, const float* __restrict__ A, int lda,
                                           __half* __restrict__ Ah) {
    int row = i >> 7, c4 = (i & 127) * 4;
    const float* ap = A + (size_t)row * lda + c4;
    __half2 H0 = {__float2half_rn(ap[0]), __float2half_rn(ap[1])};
    __half2 H1 = {__float2half_rn(ap[2]), __float2half_rn(ap[3])};
    *(uint2*)&Ah[(size_t)row * 512 + c4] = make_uint2(*(unsigned*)&H0, *(unsigned*)&H1);
}

// linear-256-thread W transpose+convert tile (32x32)
__device__ __forceinline__ void splitWT_body(int tile, int tid,
                                             const float* __restrict__ W,
                                             __half* __restrict__ T,
                                             float (*t)[33]) {
    int bn = (tile & 15) * 32, bk = (tile >> 4) * 32;
    int tx = tid & 31, ty = tid >> 5;    // 8 rows of 32
#pragma unroll
    for (int i = 0; i < 4; i++) {
        int k = bk + ty + i * 8;
        t[ty + i * 8][tx] = W[(size_t)k * 512 + bn + tx];
    }
    __syncthreads();
#pragma unroll
    for (int i = 0; i < 4; i++) {
        int n = bn + ty + i * 8;
        T[(size_t)n * 512 + bk + tx] = __float2half_rn(t[tx][ty + i * 8]);
    }
}

// ---------------- L1: fused prep (convA + 2x splitWT + hist) ----------------
__global__ void __launch_bounds__(256) prep_kernel(
    const float* __restrict__ x, const int* __restrict__ ei,
    const float* __restrict__ Wl, const float* __restrict__ Wr,
    __half* __restrict__ Ah)
{
    __shared__ float t[32][33];
    int b = blockIdx.x, tid = threadIdx.x;
    if (b < 8192) {
        convA_body(b * 256 + tid, x + 1, D1, Ah);
    } else if (b < 8448) {
        splitWT_body(b - 8192, tid, Wl, g_W1t, t);
    } else if (b < 8704) {
        splitWT_body(b - 8448, tid, Wr, g_W2t, t);
    } else {
        int i = (b - 8704) * 256 + tid;
        if (i < ETOT) {
            int dst = (i < EDG) ? ei[EDG + i] : (i - EDG);
            atomicAdd(&g_deg[dst], 1);
        }
    }
}

// ---------------- L2: scan (also re-zeros g_deg for next run) ----------------
__global__ void scan_kernel() {
    __shared__ int part[1024];
    int t = threadIdx.x;
    int loc[16];
    int s = 0;
#pragma unroll
    for (int i = 0; i < 16; i++) { loc[i] = s; s += g_deg[t * 16 + i]; }
    part[t] = s;
    __syncthreads();
    for (int d = 1; d < 1024; d <<= 1) {
        int v = (t >= d) ? part[t - d] : 0;
        __syncthreads();
        part[t] += v;
        __syncthreads();
    }
    int base = (t > 0) ? part[t - 1] : 0;
#pragma unroll
    for (int i = 0; i < 16; i++) {
        int o = base + loc[i];
        g_off[t * 16 + i] = o;
        g_cur[t * 16 + i] = o;
        g_deg[t * 16 + i] = 0;           // self-clean for next execution
    }
    if (t == 1023) g_off[NV] = part[1023];
}

// ---------------- GEMM body (fp16, fp32 accum, BK=64, dual-output) ----------
constexpr int ASTR    = 72;
constexpr int TILE_E  = 128 * ASTR;
constexpr int GEMM_SMEM = 2 * 2 * TILE_E * 2;  // 73728 B

__device__ __forceinline__ void gemm_body(
    int bx, const __half* __restrict__ Ah,
    const __half* __restrict__ W1, const __half* __restrict__ W2,
    const float* __restrict__ b1, const float* __restrict__ b2,
    float* __restrict__ C1, float* __restrict__ C2, __half* smem)
{
    const int tid  = threadIdx.x;
    const int lane = tid & 31;
    const int warp = tid >> 5;
    const int wm   = warp >> 2;
    const int wn   = warp & 3;
    const int bm   = (bx >> 3) * 128;
    const int sub  = bx & 7;
    const bool second = (sub >= 4);
    const int bn   = (sub & 3) * 128;

    const __half* Wt  = second ? W2 : W1;
    const float* bias = second ? b2 : b1;
    float* C          = second ? C2 : C1;

    const __half* gsrc[2] = { Ah + (size_t)bm * 512, Wt + (size_t)bn * 512 };

    float acc[4][4][4];
#pragma unroll
    for (int mt = 0; mt < 4; mt++)
#pragma unroll
        for (int nt = 0; nt < 4; nt++)
#pragma unroll
            for (int q = 0; q < 4; q++) acc[mt][nt][q] = 0.f;

    auto load_tile = [&](int buf, int k0) {
#pragma unroll
        for (int i = 0; i < 8; i++) {
            int id  = tid + i * 256;
            int arr = id >> 10;
            int w   = id & 1023;
            int r   = w >> 3;
            int c16 = w & 7;
            __half* s = smem + (buf * 2 + arr) * TILE_E;
            cp16(smem_u32(s + r * ASTR + c16 * 8),
                 gsrc[arr] + (size_t)r * 512 + k0 + c16 * 8);
        }
        asm volatile("cp.async.commit_group;");
    };

    load_tile(0, 0);

    for (int t = 0; t < 8; t++) {
        int buf = t & 1;
        if (t < 7) load_tile(buf ^ 1, (t + 1) * 64);
        if (t < 7) asm volatile("cp.async.wait_group 1;");
        else       asm volatile("cp.async.wait_group 0;");
        __syncthreads();

        const __half* sA = smem + (buf * 2 + 0) * TILE_E;
        const __half* sB = smem + (buf * 2 + 1) * TILE_E;

#pragma unroll
        for (int ks = 0; ks < 4; ks++) {
            unsigned bf[4][2];
#pragma unroll
            for (int nt = 0; nt < 4; nt++) {
                int n = wn * 32 + nt * 8 + (lane & 7);
                int k = ks * 16 + ((lane >> 3) & 1) * 8;
                ldmat_x2(bf[nt], smem_u32(sB + n * ASTR + k));
            }
#pragma unroll
            for (int mt = 0; mt < 4; mt++) {
                int m = wm * 64 + mt * 16 + ((lane >> 3) & 1) * 8 + (lane & 7);
                int k = ks * 16 + ((lane >> 4) & 1) * 8;
                unsigned af[4];
                ldmat_x4(af, smem_u32(sA + m * ASTR + k));
#pragma unroll
                for (int nt = 0; nt < 4; nt++)
                    mma16816h(acc[mt][nt], af, bf[nt]);
            }
        }
        __syncthreads();
    }

    const int g  = lane >> 2;
    const int t4 = lane & 3;
#pragma unroll
    for (int mt = 0; mt < 4; mt++) {
#pragma unroll
        for (int nt = 0; nt < 4; nt++) {
            int row = bm + wm * 64 + mt * 16 + g;
            int col = bn + wn * 32 + nt * 8 + 2 * t4;
            float2 bv = *(const float2*)&bias[col];
            float2 o0 = make_float2(acc[mt][nt][0] + bv.x, acc[mt][nt][1] + bv.y);
            float2 o1 = make_float2(acc[mt][nt][2] + bv.x, acc[mt][nt][3] + bv.y);
            *(float2*)&C[(size_t)row * 512 + col] = o0;
            *(float2*)&C[(size_t)(row + 8) * 512 + col] = o1;
        }
    }
}

// ---------------- L3: fused scatter + dual GEMM ----------------
__global__ void __launch_bounds__(256, 2) scatter_gemm_kernel(
    const int* __restrict__ ei, const __half* __restrict__ Ah,
    const __half* __restrict__ W1, const __half* __restrict__ W2,
    const float* __restrict__ b1, const float* __restrict__ b2,
    float* __restrict__ C1, float* __restrict__ C2)
{
    extern __shared__ __half smem[];
    if (blockIdx.x < 576) {
        int i = blockIdx.x * 256 + threadIdx.x;
        if (i >= ETOT) return;
        int s, d;
        if (i < EDG) { s = ei[i]; d = ei[EDG + i]; }
        else         { s = d = i - EDG; }
        int p = atomicAdd(&g_cur[d], 1);
        g_srcv[p] = s;
        return;
    }
    gemm_body(blockIdx.x - 576, Ah, W1, W2, b1, b2, C1, C2, smem);
}

// standalone dual GEMM (layer 2)
__global__ void __launch_bounds__(256, 2) gemm_dual_kernel(
    const __half* __restrict__ Ah,
    const __half* __restrict__ W1, const __half* __restrict__ W2,
    const float* __restrict__ b1, const float* __restrict__ b2,
    float* __restrict__ C1, float* __restrict__ C2)
{
    extern __shared__ __half smem[];
    gemm_body(blockIdx.x, Ah, W1, W2, b1, b2, C1, C2, smem);
}

// fused W-pair transpose for layer 2
__global__ void __launch_bounds__(256) splitW_both_kernel(
    const float* __restrict__ Wl, const float* __restrict__ Wr)
{
    __shared__ float t[32][33];
    int b = blockIdx.x, tid = threadIdx.x;
    if (b < 256) splitWT_body(b, tid, Wl, g_W1t, t);
    else         splitWT_body(b - 256, tid, Wr, g_W2t, t);
}

// ---------------- small-M GEMM (MLP tail) ----------------
__global__ void gemm_small_kernel(
    const float* __restrict__ A, int lda,
    const float* __restrict__ W,
    const float* __restrict__ bias,
    float* __restrict__ C, int M, int Nc, int K)
{
    int n = blockIdx.x * blockDim.x + threadIdx.x;
    int m0 = blockIdx.y * 4;
    if (n >= Nc || m0 >= M) return;
    const float* a0 = A + (size_t)m0 * lda;
    const float* a1 = a0 + lda;
    const float* a2 = a1 + lda;
    const float* a3 = a2 + lda;
    float s0 = 0.f, s1 = 0.f, s2 = 0.f, s3 = 0.f;
    for (int k = 0; k < K; k++) {
        float w = W[(size_t)k * Nc + n];
        s0 += a0[k] * w; s1 += a1[k] * w; s2 += a2[k] * w; s3 += a3[k] * w;
    }
    float bv = bias[n];
    C[(size_t)(m0 + 0) * Nc + n] = s0 + bv;
    C[(size_t)(m0 + 1) * Nc + n] = s1 + bv;
    C[(size_t)(m0 + 2) * Nc + n] = s2 + bv;
    C[(size_t)(m0 + 3) * Nc + n] = s3 + bv;
}

// ---------------- fused GATv2, 2-stream + prefetch pipeline ----------------
__global__ void __launch_bounds__(128) gat_kernel(
    const float* __restrict__ xl, const float* __restrict__ xr,
    const float* __restrict__ att, const float* __restrict__ bias,
    float* __restrict__ out, __half* __restrict__ out16, int mode)
{
    int dst = blockIdx.x;
    int w = threadIdx.x >> 5;
    int l = threadIdx.x & 31;
    int start = g_off[dst];
    int end   = g_off[dst + 1];

    float4 xrr  = ((const float4*)(xr  + (size_t)dst * HC + w * CC))[l];
    float4 attr = ((const float4*)(att + w * CC))[l];

    float mx0 = -1e30f, den0 = 0.f;
    float4 A0 = make_float4(0.f, 0.f, 0.f, 0.f);
    float mx1 = -1e30f, den1 = 0.f;
    float4 A1 = make_float4(0.f, 0.f, 0.f, 0.f);

    const float* xb = xl + w * CC;

    for (int c0 = start; c0 < end; c0 += 32) {
        int myi = c0 + l;
        int mysrc = (myi < end) ? g_srcv[myi] : 0;
        int lim = end - c0; if (lim > 32) lim = 32;

        // prime the pipeline
        float4 xv0, xv1;
        {
            int s = __shfl_sync(0xffffffffu, mysrc, 0);
            xv0 = ((const float4*)(xb + (size_t)s * HC))[l];
        }
        if (lim > 1) {
            int s = __shfl_sync(0xffffffffu, mysrc, 1);
            xv1 = ((const float4*)(xb + (size_t)s * HC))[l];
        }

        for (int jj = 0; jj < lim; jj += 2) {
            float4 cv0 = xv0, cv1 = xv1;
            bool has1 = (jj + 1 < lim);
            int nj = jj + 2;
            if (nj < lim) {                       // prefetch next pair
                int s = __shfl_sync(0xffffffffu, mysrc, nj);
                xv0 = ((const float4*)(xb + (size_t)s * HC))[l];
                if (nj + 1 < lim) {
                    int s2 = __shfl_sync(0xffffffffu, mysrc, nj + 1);
                    xv1 = ((const float4*)(xb + (size_t)s2 * HC))[l];
                }
            }
            // stream 0
            {
                float v0 = cv0.x + xrr.x; v0 = (v0 > 0.f) ? v0 : 0.2f * v0;
                float v1 = cv0.y + xrr.y; v1 = (v1 > 0.f) ? v1 : 0.2f * v1;
                float v2 = cv0.z + xrr.z; v2 = (v2 > 0.f) ? v2 : 0.2f * v2;
                float v3 = cv0.w + xrr.w; v3 = (v3 > 0.f) ? v3 : 0.2f * v3;
                float a = v0 * attr.x + v1 * attr.y + v2 * attr.z + v3 * attr.w;
#pragma unroll
                for (int o = 16; o; o >>= 1) a += __shfl_xor_sync(0xffffffffu, a, o);
                float nm = fmaxf(mx0, a);
                float sc = __expf(mx0 - nm);
                float ew = __expf(a - nm);
                den0 = den0 * sc + ew;
                A0.x = A0.x * sc + ew * cv0.x;
                A0.y = A0.y * sc + ew * cv0.y;
                A0.z = A0.z * sc + ew * cv0.z;
                A0.w = A0.w * sc + ew * cv0.w;
                mx0 = nm;
            }
            // stream 1
            if (has1) {
                float v0 = cv1.x + xrr.x; v0 = (v0 > 0.f) ? v0 : 0.2f * v0;
                float v1 = cv1.y + xrr.y; v1 = (v1 > 0.f) ? v1 : 0.2f * v1;
                float v2 = cv1.z + xrr.z; v2 = (v2 > 0.f) ? v2 : 0.2f * v2;
                float v3 = cv1.w + xrr.w; v3 = (v3 > 0.f) ? v3 : 0.2f * v3;
                float a = v0 * attr.x + v1 * attr.y + v2 * attr.z + v3 * attr.w;
#pragma unroll
                for (int o = 16; o; o >>= 1) a += __shfl_xor_sync(0xffffffffu, a, o);
                float nm = fmaxf(mx1, a);
                float sc = __expf(mx1 - nm);
                float ew = __expf(a - nm);
                den1 = den1 * sc + ew;
                A1.x = A1.x * sc + ew * cv1.x;
                A1.y = A1.y * sc + ew * cv1.y;
                A1.z = A1.z * sc + ew * cv1.z;
                A1.w = A1.w * sc + ew * cv1.w;
                mx1 = nm;
            }
        }
    }

    // merge streams
    float nm = fmaxf(mx0, mx1);
    float s0 = __expf(mx0 - nm), s1 = __expf(mx1 - nm);
    float den = den0 * s0 + den1 * s1;
    float4 acc;
    acc.x = A0.x * s0 + A1.x * s1;
    acc.y = A0.y * s0 + A1.y * s1;
    acc.z = A0.z * s0 + A1.z * s1;
    acc.w = A0.w * s0 + A1.w * s1;

    float inv = 1.0f / (den + 1e-16f);
    float4 bv = ((const float4*)(bias + w * CC))[l];
    float v[4];
    v[0] = acc.x * inv + bv.x;
    v[1] = acc.y * inv + bv.y;
    v[2] = acc.z * inv + bv.z;
    v[3] = acc.w * inv + bv.w;

    if (mode == 0) {
        float g0 = 0.5f * v[0] * (1.0f + erff(v[0] * 0.70710678118654752f));
        float g1 = 0.5f * v[1] * (1.0f + erff(v[1] * 0.70710678118654752f));
        float g2 = 0.5f * v[2] * (1.0f + erff(v[2] * 0.70710678118654752f));
        float g3 = 0.5f * v[3] * (1.0f + erff(v[3] * 0.70710678118654752f));
        __half2 H0 = {__float2half_rn(g0), __float2half_rn(g1)};
        __half2 H1 = {__float2half_rn(g2), __float2half_rn(g3)};
        *(uint2*)(out16 + (size_t)dst * HC + w * CC + 4 * l) =
            make_uint2(*(unsigned*)&H0, *(unsigned*)&H1);
    } else {
        float sq = v[0] * v[0] + v[1] * v[1] + v[2] * v[2] + v[3] * v[3];
#pragma unroll
        for (int o = 16; o; o >>= 1) sq += __shfl_xor_sync(0xffffffffu, sq, o);
        __shared__ float red[4];
        if (l == 0) red[w] = sq;
        __syncthreads();
        float tot = red[0] + red[1] + red[2] + red[3];
        if (threadIdx.x == 0) out[(size_t)dst * D1] = sqrtf(1.0f + tot);
        float* op = out + (size_t)dst * D1 + 1 + w * CC + 4 * l;
        op[0] = v[0]; op[1] = v[1]; op[2] = v[2]; op[3] = v[3];
    }
}

// ---------------- centroid per batch ----------------
__global__ void __launch_bounds__(256) centroid_kernel(
    const float* __restrict__ h3, float* __restrict__ gm)
{
    int b = blockIdx.x;
    __shared__ float avg[D1];
    const float* basep = h3 + (size_t)b * 128 * D1;
    for (int c = threadIdx.x; c < D1; c += blockDim.x) {
        float s = 0.f;
        for (int r = 0; r < 128; r++) s += basep[(size_t)r * D1 + c];
        avg[c] = s * (1.0f / 128.0f);
    }
    __syncthreads();
    float loc = 0.f;
    for (int c = threadIdx.x; c < D1; c += blockDim.x) {
        float a = avg[c];
        loc += (c == 0) ? -a * a : a * a;
    }
#pragma unroll
    for (int o = 16; o; o >>= 1) loc += __shfl_xor_sync(0xffffffffu, loc, o);
    __shared__ float red[8];
    int w = threadIdx.x >> 5, l = threadIdx.x & 31;
    if (l == 0) red[w] = loc;
    __syncthreads();
    __shared__ float s_invden;
    if (threadIdx.x == 0) {
        float inner = 0.f;
        for (int i = 0; i < 8; i++) inner += red[i];
        s_invden = 1.0f / sqrtf(fmaxf(-inner, 1e-8f));
    }
    __syncthreads();
    float invd = s_invden;
    for (int c = threadIdx.x; c < D1; c += blockDim.x)
        gm[(size_t)b * D1 + c] = avg[c] * invd;
}

// ---------------- llin epilogue ----------------
__global__ void __launch_bounds__(256) llin_post_kernel(
    const float* __restrict__ zin, float* __restrict__ zout,
    const float* __restrict__ sptr, int D)
{
    int b = blockIdx.x;
    const float* row = zin + (size_t)b * D;
    float loc = 0.f;
    for (int c = 1 + threadIdx.x; c < D; c += blockDim.x) { float v = row[c]; loc += v * v; }
#pragma unroll
    for (int o = 16; o; o >>= 1) loc += __shfl_xor_sync(0xffffffffu, loc, o);
    __shared__ float red[8];
    int w = threadIdx.x >> 5, l = threadIdx.x & 31;
    if (l == 0) red[w] = loc;
    __syncthreads();
    __shared__ float s_t, s_scale;
    if (threadIdx.x == 0) {
        float sq = 0.f;
        for (int i = 0; i < 8; i++) sq += red[i];
        sq = fmaxf(sq, 1e-8f);
        float z0 = row[0];
        float t = (1.0f / (1.0f + expf(-z0))) * expf(*sptr) + 1.1f;
        s_t = t;
        s_scale = sqrtf((t * t - 1.0f) / sq);
    }
    __syncthreads();
    if (threadIdx.x == 0) zout[(size_t)b * D] = s_t;
    float sc = s_scale;
    for (int c = 1 + threadIdx.x; c < D; c += blockDim.x)
        zout[(size_t)b * D + c] = row[c] * sc;
}

// ---------------- gelu + add_time ----------------
__global__ void __launch_bounds__(256) gelu_addtime_kernel(
    const float* __restrict__ zin, float* __restrict__ zout, int D)
{
    int b = blockIdx.x;
    const float* row = zin + (size_t)b * D;
    float* orow = zout + (size_t)b * D;
    float loc = 0.f;
    for (int c = 1 + threadIdx.x; c < D; c += blockDim.x) {
        float x = row[c];
        float g = 0.5f * x * (1.0f + erff(x * 0.70710678118654752f));
        orow[c] = g;
        loc += g * g;
    }
#pragma unroll
    for (int o = 16; o; o >>= 1) loc += __shfl_xor_sync(0xffffffffu, loc, o);
    __shared__ float red[8];
    int w = threadIdx.x >> 5, l = threadIdx.x & 31;
    if (l == 0) red[w] = loc;
    __syncthreads();
    if (threadIdx.x == 0) {
        float tot = 0.f;
        for (int i = 0; i < 8; i++) tot += red[i];
        orow[0] = sqrtf(1.0f + tot);
    }
}

// ---------------- launch ----------------
extern "C" void kernel_launch(void* const* d_in, const int* in_sizes, int n_in,
                              void* d_out, int out_size)
{
    const float* x  = (const float*)d_in[0];
    const int*   ei = (const int*)d_in[1];
    int base = 2;
    if (n_in > 2 && in_sizes[2] == 1) base = 3;

    const float* Wl1   = (const float*)d_in[base + 0];
    const float* bl1   = (const float*)d_in[base + 1];
    const float* Wr1   = (const float*)d_in[base + 2];
    const float* br1   = (const float*)d_in[base + 3];
    const float* att1  = (const float*)d_in[base + 4];
    const float* bias1 = (const float*)d_in[base + 5];
    const float* Wl2   = (const float*)d_in[base + 6];
    const float* bl2   = (const float*)d_in[base + 7];
    const float* Wr2   = (const float*)d_in[base + 8];
    const float* br2   = (const float*)d_in[base + 9];
    const float* att2  = (const float*)d_in[base + 10];
    const float* bias2 = (const float*)d_in[base + 11];
    const float* Wa    = (const float*)d_in[base + 12];
    const float* ba    = (const float*)d_in[base + 13];
    const float* sa    = (const float*)d_in[base + 14];
    const float* Wb    = (const float*)d_in[base + 15];
    const float* bb    = (const float*)d_in[base + 16];
    const float* sb    = (const float*)d_in[base + 17];
    const float* Wf    = (const float*)d_in[base + 18];
    const float* bf    = (const float*)d_in[base + 19];
    const float* sf    = (const float*)d_in[base + 20];

    float* out = (float*)d_out;

    void* p;
    cudaGetSymbolAddress(&p, g_xl); float* pxl = (float*)p;
    cudaGetSymbolAddress(&p, g_xr); float* pxr = (float*)p;
    cudaGetSymbolAddress(&p, g_h3); float* ph3 = (float*)p;
    cudaGetSymbolAddress(&p, g_za); float* pza = (float*)p;
    cudaGetSymbolAddress(&p, g_z1); float* pz1 = (float*)p;
    cudaGetSymbolAddress(&p, g_z2); float* pz2 = (float*)p;
    cudaGetSymbolAddress(&p, g_zb); float* pzb = (float*)p;
    cudaGetSymbolAddress(&p, g_z3); float* pz3 = (float*)p;
    cudaGetSymbolAddress(&p, g_zf); float* pzf = (float*)p;
    cudaGetSymbolAddress(&p, g_A16); __half* pA  = (__half*)p;
    cudaGetSymbolAddress(&p, g_W1t); __half* pW1 = (__half*)p;
    cudaGetSymbolAddress(&p, g_W2t); __half* pW2 = (__half*)p;

    static bool attr_set = false;
    if (!attr_set) {
        cudaFuncSetAttribute(gemm_dual_kernel,
                             cudaFuncAttributeMaxDynamicSharedMemorySize, GEMM_SMEM);
        cudaFuncSetAttribute(scatter_gemm_kernel,
                             cudaFuncAttributeMaxDynamicSharedMemorySize, GEMM_SMEM);
        attr_set = true;
    }

    // L1: convA + splitWT(Wl1) + splitWT(Wr1) + hist (deg zeroed by prev scan)
    prep_kernel<<<9280, 256>>>(x, ei, Wl1, Wr1, pA);
    // L2: scan (also re-zeros deg)
    scan_kernel<<<1, 1024>>>();
    // L3: scatter + layer-1 dual GEMM
    scatter_gemm_kernel<<<576 + 1024, 256, GEMM_SMEM>>>(ei, pA, pW1, pW2, bl1, br1, pxl, pxr);
    // L4: layer-1 GAT (-> profiled)
    gat_kernel<<<NV, 128>>>(pxl, pxr, att1, bias1, nullptr, pA, 0);

    // layer 2
    splitW_both_kernel<<<512, 256>>>(Wl2, Wr2);
    gemm_dual_kernel<<<dim3(8 * 128), 256, GEMM_SMEM>>>(pA, pW1, pW2, bl2, br2, pxl, pxr);
    gat_kernel<<<NV, 128>>>(pxl, pxr, att2, bias2, ph3, nullptr, 1);

    // centroid -> second half of output
    centroid_kernel<<<BB, 256>>>(ph3, out + (size_t)BB * D1);

    // MLP head
    gemm_small_kernel<<<dim3((DA + 255) / 256, BB / 4), 256>>>(ph3, 128 * D1, Wa, ba, pza, BB, DA, D1);
    llin_post_kernel<<<BB, 256>>>(pza, pz1, sa, DA);
    gelu_addtime_kernel<<<BB, 256>>>(pz1, pz2, DA);
    gemm_small_kernel<<<dim3((D1 + 255) / 256, BB / 4), 256>>>(pz2, DA, Wb, bb, pzb, BB, D1, DA);
    llin_post_kernel<<<BB, 256>>>(pzb, pz3, sb, D1);
    gemm_small_kernel<<<dim3((D1 + 255) / 256, BB / 4), 256>>>(pz3, D1, Wf, bf, pzf, BB, D1, D1);
    llin_post_kernel<<<BB, 256>>>(pzf, out, sf, D1);

    (void)out_size;
}